// round 1
// baseline (speedup 1.0000x reference)
#include <cuda_runtime.h>
#include <math.h>

// Problem constants
#define NXC 32
#define NYC 32
#define NZC 32
#define NBC 16
#define LMEM 64
#define MID 128
#define NSITE (NXC*NYC*NZC*NBC)   // 524288

#define TILE 128                  // sites per block-tile
#define NTHREADS 512
#define NTILES (NSITE / TILE)     // 4096
#define MLP_GRID 148

// scratch for the nearest-neighbor MLP output (2 MB, static device global)
__device__ float g_xnn[NSITE];

// ---------------------------------------------------------------------------
// Fused 3-layer Tanh MLP over all sites.
//   out[site] = tanh(W3 . tanh(W2 . tanh(W1' . x + b1) + b2) + b3) * max_os
//               (+ dot(x, ag) if add_ar)
// W1' = W1 * weight (weight vector folded into W1 at smem load time).
// Thread layout: tid = o*16 + g ; o in [0,32) -> outputs 4o..4o+3,
//                g in [0,16) -> sites g*8..g*8+7  (4x8 = 32 accumulators).
// ---------------------------------------------------------------------------
__global__ __launch_bounds__(NTHREADS, 1)
void mlp_kernel(const float* __restrict__ xg,
                const float* __restrict__ weight,
                const float* __restrict__ W1, const float* __restrict__ b1,
                const float* __restrict__ W2, const float* __restrict__ b2,
                const float* __restrict__ W3, const float* __restrict__ b3,
                const float* __restrict__ ag,
                const float* __restrict__ max_os_l,
                float* __restrict__ outp,
                int add_ar)
{
    extern __shared__ float sm[];
    float* sW1 = sm;                    // [64][128]  transposed, weight-folded
    float* sW2 = sW1 + LMEM * MID;      // [128][128] transposed (W2T[m][n])
    float* sX  = sW2 + MID * MID;       // [64][128]  l-major, site-fastest
    float* sH  = sX  + LMEM * TILE;     // [128][128] hidden, out-major, site-fastest

    __shared__ float sb1[MID], sb2[MID], sW3[MID], sAg[LMEM];

    const int tid = threadIdx.x;

    // ---- load weights into smem (once per block) ----
    for (int i = tid; i < LMEM * MID; i += NTHREADS) {
        int l = i >> 7, n = i & 127;
        sW1[l * MID + n] = W1[n * LMEM + l] * weight[l];
    }
    for (int i = tid; i < MID * MID; i += NTHREADS) {
        int m = i >> 7, n = i & 127;
        sW2[m * MID + n] = W2[n * MID + m];
    }
    if (tid < MID) { sb1[tid] = b1[tid]; sb2[tid] = b2[tid]; sW3[tid] = W3[tid]; }
    if (tid < LMEM) sAg[tid] = add_ar ? ag[tid] : 0.0f;

    const float max_os = expf(max_os_l[0]);
    const float bias3  = b3[0];
    __syncthreads();

    const int o = tid >> 4;   // 0..31
    const int g = tid & 15;   // 0..15

    const float* wp1 = sW1 + 4 * o;
    const float* wp2 = sW2 + 4 * o;
    const float* xp  = sX + g * 8;
    const float* hp  = sH + g * 8;

    for (int tile = blockIdx.x; tile < NTILES; tile += gridDim.x) {
        const int base = tile * TILE;

        // ---- stage x tile transposed: sX[l*128 + s] = x[(base+s)*64 + l] ----
        // s fastest in idx -> conflict-free STS (bank = s % 32).
        {
            const float4* xg4 = (const float4*)(xg + (size_t)base * LMEM);
            #pragma unroll
            for (int it = 0; it < (16 * TILE) / NTHREADS; it++) {
                int idx = tid + it * NTHREADS;
                int s  = idx & 127;
                int lq = idx >> 7;          // 0..15 (float4 group along l)
                float4 v = xg4[s * 16 + lq];
                sX[(4 * lq + 0) * TILE + s] = v.x;
                sX[(4 * lq + 1) * TILE + s] = v.y;
                sX[(4 * lq + 2) * TILE + s] = v.z;
                sX[(4 * lq + 3) * TILE + s] = v.w;
            }
        }
        __syncthreads();

        // ---- layer 1: 64 -> 128 ----
        float acc[4][8];
        #pragma unroll
        for (int j = 0; j < 4; j++)
            #pragma unroll
            for (int i = 0; i < 8; i++) acc[j][i] = 0.0f;

        #pragma unroll 4
        for (int l = 0; l < LMEM; l++) {
            float4 w  = *(const float4*)(wp1 + l * MID);
            float4 xa = *(const float4*)(xp + l * TILE);
            float4 xb = *(const float4*)(xp + l * TILE + 4);
            float wv[4] = {w.x, w.y, w.z, w.w};
            float xv[8] = {xa.x, xa.y, xa.z, xa.w, xb.x, xb.y, xb.z, xb.w};
            #pragma unroll
            for (int j = 0; j < 4; j++)
                #pragma unroll
                for (int i = 0; i < 8; i++)
                    acc[j][i] = fmaf(wv[j], xv[i], acc[j][i]);
        }

        // h1 = tanh(acc + b1) -> sH
        {
            float4 bv = *(const float4*)(sb1 + 4 * o);
            float bj[4] = {bv.x, bv.y, bv.z, bv.w};
            #pragma unroll
            for (int j = 0; j < 4; j++) {
                float h0 = tanhf(acc[j][0] + bj[j]);
                float h1v = tanhf(acc[j][1] + bj[j]);
                float h2 = tanhf(acc[j][2] + bj[j]);
                float h3 = tanhf(acc[j][3] + bj[j]);
                float h4 = tanhf(acc[j][4] + bj[j]);
                float h5 = tanhf(acc[j][5] + bj[j]);
                float h6 = tanhf(acc[j][6] + bj[j]);
                float h7 = tanhf(acc[j][7] + bj[j]);
                *(float4*)(sH + (4 * o + j) * TILE + g * 8)     = make_float4(h0, h1v, h2, h3);
                *(float4*)(sH + (4 * o + j) * TILE + g * 8 + 4) = make_float4(h4, h5, h6, h7);
            }
        }
        __syncthreads();

        // ---- layer 2: 128 -> 128 ----
        #pragma unroll
        for (int j = 0; j < 4; j++)
            #pragma unroll
            for (int i = 0; i < 8; i++) acc[j][i] = 0.0f;

        #pragma unroll 4
        for (int m = 0; m < MID; m++) {
            float4 w  = *(const float4*)(wp2 + m * MID);
            float4 ha = *(const float4*)(hp + m * TILE);
            float4 hb = *(const float4*)(hp + m * TILE + 4);
            float wv[4] = {w.x, w.y, w.z, w.w};
            float hv[8] = {ha.x, ha.y, ha.z, ha.w, hb.x, hb.y, hb.z, hb.w};
            #pragma unroll
            for (int j = 0; j < 4; j++)
                #pragma unroll
                for (int i = 0; i < 8; i++)
                    acc[j][i] = fmaf(wv[j], hv[i], acc[j][i]);
        }
        __syncthreads();   // everyone done READING sH before we overwrite it

        // h2 = tanh(acc + b2) -> sH
        {
            float4 bv = *(const float4*)(sb2 + 4 * o);
            float bj[4] = {bv.x, bv.y, bv.z, bv.w};
            #pragma unroll
            for (int j = 0; j < 4; j++) {
                float h0 = tanhf(acc[j][0] + bj[j]);
                float h1v = tanhf(acc[j][1] + bj[j]);
                float h2 = tanhf(acc[j][2] + bj[j]);
                float h3 = tanhf(acc[j][3] + bj[j]);
                float h4 = tanhf(acc[j][4] + bj[j]);
                float h5 = tanhf(acc[j][5] + bj[j]);
                float h6 = tanhf(acc[j][6] + bj[j]);
                float h7 = tanhf(acc[j][7] + bj[j]);
                *(float4*)(sH + (4 * o + j) * TILE + g * 8)     = make_float4(h0, h1v, h2, h3);
                *(float4*)(sH + (4 * o + j) * TILE + g * 8 + 4) = make_float4(h4, h5, h6, h7);
            }
        }
        __syncthreads();

        // ---- layer 3: 128 -> 1 (4 threads per site) + AR term ----
        {
            const int s3 = tid >> 2;   // 0..127
            const int q  = tid & 3;    // 0..3
            float p = 0.0f;
            #pragma unroll 8
            for (int m = 32 * q; m < 32 * q + 32; m++)
                p = fmaf(sW3[m], sH[m * TILE + s3], p);
            float arp = 0.0f;
            if (add_ar) {
                #pragma unroll 8
                for (int l = 16 * q; l < 16 * q + 16; l++)
                    arp = fmaf(sAg[l], sX[l * TILE + s3], arp);
            }
            p   += __shfl_xor_sync(0xffffffffu, p, 1);
            p   += __shfl_xor_sync(0xffffffffu, p, 2);
            arp += __shfl_xor_sync(0xffffffffu, arp, 1);
            arp += __shfl_xor_sync(0xffffffffu, arp, 2);
            if (q == 0)
                outp[base + s3] = tanhf(p + bias3) * max_os + arp;
        }
        __syncthreads();   // sX/sH reads done before next tile overwrites
    }
}

// ---------------------------------------------------------------------------
// Stencil + sigma kernel.
// out[i] += (8 periodic neighbors of xnn)/8 ; out[N+i] = exp(sigma_l)
// site index: (((x*32+y)*32+z)*16+b)
// ---------------------------------------------------------------------------
__global__ void stencil_kernel(const float* __restrict__ xnn,
                               const float* __restrict__ sigma_l,
                               float* __restrict__ outp)
{
    int i = blockIdx.x * blockDim.x + threadIdx.x;
    if (i >= NSITE) return;
    int b = i & 15;
    int z = (i >> 4) & 31;
    int y = (i >> 9) & 31;
    int x = (i >> 14) & 31;
    int xm = (x + 31) & 31, xp = (x + 1) & 31;
    int ym = (y + 31) & 31, yp = (y + 1) & 31;
    int zm = (z + 31) & 31, zp = (z + 1) & 31;

    #define SIDX(X, Y, Z, B) (((((X) << 5) + (Y)) << 5) + (Z)) * 16 + (B)
    float s = xnn[SIDX(xm, y, zm, b)] + xnn[SIDX(xm, y, zp, b)]
            + xnn[SIDX(xp, y, zm, b)] + xnn[SIDX(xp, y, zp, b)]
            + xnn[SIDX(x, ym, zm, b)] + xnn[SIDX(x, ym, zp, b)]
            + xnn[SIDX(x, yp, zm, b)] + xnn[SIDX(x, yp, zp, b)];
    #undef SIDX

    outp[i] = outp[i] + s * 0.125f;
    outp[NSITE + i] = expf(sigma_l[0]);
}

// ---------------------------------------------------------------------------
extern "C" void kernel_launch(void* const* d_in, const int* in_sizes, int n_in,
                              void* d_out, int out_size)
{
    const float* x_in    = (const float*)d_in[0];
    const float* weight  = (const float*)d_in[1];
    const float* ag      = (const float*)d_in[2];
    const float* W1      = (const float*)d_in[3];
    const float* b1      = (const float*)d_in[4];
    const float* W2      = (const float*)d_in[5];
    const float* b2      = (const float*)d_in[6];
    const float* W3      = (const float*)d_in[7];
    const float* b3      = (const float*)d_in[8];
    const float* W1n     = (const float*)d_in[9];
    const float* b1n     = (const float*)d_in[10];
    const float* W2n     = (const float*)d_in[11];
    const float* b2n     = (const float*)d_in[12];
    const float* W3n     = (const float*)d_in[13];
    const float* b3n     = (const float*)d_in[14];
    const float* max_osl = (const float*)d_in[15];
    const float* sigmal  = (const float*)d_in[16];
    float* out = (float*)d_out;

    const size_t smem = (size_t)(LMEM * MID + MID * MID + LMEM * TILE + MID * TILE) * sizeof(float); // 192 KB
    cudaFuncSetAttribute(mlp_kernel, cudaFuncAttributeMaxDynamicSharedMemorySize, (int)smem);

    float* xnn;
    cudaGetSymbolAddress((void**)&xnn, g_xnn);

    // onsite MLP (+AR) -> out[0:N]
    mlp_kernel<<<MLP_GRID, NTHREADS, smem>>>(x_in, weight, W1, b1, W2, b2, W3, b3,
                                             ag, max_osl, out, 1);
    // nearest-neighbor MLP -> scratch
    mlp_kernel<<<MLP_GRID, NTHREADS, smem>>>(x_in, weight, W1n, b1n, W2n, b2n, W3n, b3n,
                                             ag, max_osl, xnn, 0);
    // stencil combine + sigma plane
    stencil_kernel<<<(NSITE + 255) / 256, 256>>>(xnn, sigmal, out);
}

// round 4
// speedup vs baseline: 2.4356x; 2.4356x over previous
#include <cuda_runtime.h>
#include <cuda_bf16.h>
#include <math.h>
#include <stdint.h>

#define NSITE  524288          // 32*32*32*16
#define TILE   128
#define NTILES 4096
#define GRID   148
#define NTHR   512

// ---- dynamic smem layout (bytes) ----
#define XHI_OFF    0           // [128 sites x 64 bf16] 128B rows, swizzled
#define XLO_OFF    16384
#define W1HI_OFF   32768       // [128 n x 64 k bf16]
#define W1LO_OFF   49152
#define W2HI_OFF   65536       // [128 n x 128 k bf16] blocked atoms
#define W2LO_OFF   98304
#define HHI_OFF    131072      // [128 sites x 128 mid bf16] blocked atoms
#define HLO_OFF    163840
#define B1S_OFF    196608
#define B2S_OFF    197120
#define W3S_OFF    197632
#define AGS_OFF    198144
#define PPS_OFF    198400      // 4*128 f32
#define SMEM_BYTES 200448

// swizzle: XOR bits[4:6] with bits[7:9] (conflict-free ldmatrix on 128B rows)
__device__ __forceinline__ uint32_t swz(uint32_t o) { return o ^ ((o >> 3) & 0x70); }
// 128B-row tiles (X, W1): row 0..127, colb = byte within row (0..127)
__device__ __forceinline__ uint32_t xsw(int row, int colb) {
    return swz((uint32_t)(row * 128 + colb));
}
// 256B-row tiles (H, W2) in blocked atoms: atom = (row/8) + (colb/128)*16
__device__ __forceinline__ uint32_t hsw(int row, int colb) {
    uint32_t o = (uint32_t)((((row >> 3) + (colb >> 7) * 16) << 10)
                            + ((row & 7) << 7) + (colb & 127));
    return swz(o);
}

__device__ __forceinline__ void split2(float a, float b, uint32_t& hi, uint32_t& lo) {
    __nv_bfloat162 h, l;
    h.x = __float2bfloat16_rn(a);
    h.y = __float2bfloat16_rn(b);
    l.x = __float2bfloat16_rn(a - __bfloat162float(h.x));
    l.y = __float2bfloat16_rn(b - __bfloat162float(h.y));
    hi = reinterpret_cast<uint32_t&>(h);
    lo = reinterpret_cast<uint32_t&>(l);
}

// tanh via 2 MUFU (ex2 + rcp), abs err ~2e-7
__device__ __forceinline__ float ftanh(float x) {
    float t = __expf(2.0f * x);
    return 1.0f - __fdividef(2.0f, 1.0f + t);
}

#define LDSM4(r0, r1, r2, r3, a) \
    asm volatile("ldmatrix.sync.aligned.m8n8.x4.shared.b16 {%0,%1,%2,%3}, [%4];" \
                 : "=r"(r0), "=r"(r1), "=r"(r2), "=r"(r3) : "r"(a))

__device__ __forceinline__ void mma_bf16(float* d, const uint32_t* a, const uint32_t* b) {
    asm volatile(
        "mma.sync.aligned.m16n8k16.row.col.f32.bf16.bf16.f32 "
        "{%0,%1,%2,%3},{%4,%5,%6,%7},{%8,%9},{%0,%1,%2,%3};"
        : "+f"(d[0]), "+f"(d[1]), "+f"(d[2]), "+f"(d[3])
        : "r"(a[0]), "r"(a[1]), "r"(a[2]), "r"(a[3]), "r"(b[0]), "r"(b[1]));
}

__device__ float g_xnn[NSITE];

// ---------------------------------------------------------------------------
__global__ __launch_bounds__(NTHR, 1)
void mlp_tc_kernel(const float* __restrict__ xg,
                   const float* __restrict__ weight,
                   const float* __restrict__ W1, const float* __restrict__ b1,
                   const float* __restrict__ W2, const float* __restrict__ b2,
                   const float* __restrict__ W3, const float* __restrict__ b3,
                   const float* __restrict__ ag,
                   const float* __restrict__ max_os_l,
                   float* __restrict__ outp,
                   int add_ar)
{
    extern __shared__ char smp[];
    uint32_t su;
    asm("{ .reg .u64 t; cvta.to.shared.u64 t, %1; cvt.u32.u64 %0, t; }"
        : "=r"(su) : "l"(smp));

    const int tid  = threadIdx.x;
    const int wid  = tid >> 5;
    const int lane = tid & 31;
    const int mw   = wid & 3;     // M block of 32 sites
    const int nw   = wid >> 2;    // N block of 32 outputs

    // ldmatrix lane geometry
    const int lm = lane >> 3;     // matrix id 0..3
    const int lr = lane & 7;      // row within matrix
    const int a_row = ((lm & 1) << 3) + lr;
    const int a_kb  = (lm >> 1) << 4;
    const int b_row = ((lm >> 1) << 3) + lr;
    const int b_kb  = (lm & 1) << 4;
    // epilogue geometry
    const int eg = lane >> 2;          // row group 0..7
    const int ec = (lane & 3) << 1;    // col pair base 0,2,4,6

    float* b1s = (float*)(smp + B1S_OFF);
    float* b2s = (float*)(smp + B2S_OFF);
    float* W3s = (float*)(smp + W3S_OFF);
    float* ags = (float*)(smp + AGS_OFF);
    float* pps = (float*)(smp + PPS_OFF);

    // ---- one-time weight prep (split bf16) ----
    for (int idx = tid; idx < 128 * 32; idx += NTHR) {     // W1 (weight folded in)
        int n = idx >> 5, j = idx & 31;
        float w0 = W1[n * 64 + 2 * j]     * weight[2 * j];
        float w1 = W1[n * 64 + 2 * j + 1] * weight[2 * j + 1];
        uint32_t hi, lo; split2(w0, w1, hi, lo);
        uint32_t o = xsw(n, j * 4);
        *(uint32_t*)(smp + W1HI_OFF + o) = hi;
        *(uint32_t*)(smp + W1LO_OFF + o) = lo;
    }
    for (int idx = tid; idx < 128 * 64; idx += NTHR) {     // W2
        int n = idx >> 6, j = idx & 63;
        float w0 = W2[n * 128 + 2 * j];
        float w1 = W2[n * 128 + 2 * j + 1];
        uint32_t hi, lo; split2(w0, w1, hi, lo);
        uint32_t o = hsw(n, j * 4);
        *(uint32_t*)(smp + W2HI_OFF + o) = hi;
        *(uint32_t*)(smp + W2LO_OFF + o) = lo;
    }
    if (tid < 128) { b1s[tid] = b1[tid]; b2s[tid] = b2[tid]; W3s[tid] = W3[tid]; }
    if (tid < 64)  ags[tid] = add_ar ? ag[tid] : 0.0f;

    const float max_os = expf(max_os_l[0]);
    const float b3v    = b3[0];
    __syncthreads();

    for (int tile = blockIdx.x; tile < NTILES; tile += gridDim.x) {
        const int base = tile * TILE;

        // ---- stage X tile: fp32 -> split bf16 ----
        {
            const float2* xg2 = (const float2*)(xg + (size_t)base * 64);
            #pragma unroll
            for (int it = 0; it < 8; it++) {
                int idx = tid + it * NTHR;
                int s = idx >> 5, j = idx & 31;
                float2 v = xg2[s * 32 + j];
                uint32_t hi, lo; split2(v.x, v.y, hi, lo);
                uint32_t o = xsw(s, j * 4);
                *(uint32_t*)(smp + XHI_OFF + o) = hi;
                *(uint32_t*)(smp + XLO_OFF + o) = lo;
            }
        }
        __syncthreads();

        // ---- layer 1 GEMM: 3 split products, K=64 ----
        float d1[2][4][4];
        #pragma unroll
        for (int a = 0; a < 2; a++)
            #pragma unroll
            for (int b = 0; b < 4; b++)
                #pragma unroll
                for (int c = 0; c < 4; c++) d1[a][b][c] = 0.0f;

        #pragma unroll
        for (int p = 0; p < 3; p++) {
            const uint32_t abase = su + ((p == 2) ? XLO_OFF : XHI_OFF);
            const uint32_t bbase = su + ((p == 1) ? W1LO_OFF : W1HI_OFF);
            #pragma unroll
            for (int kk = 0; kk < 4; kk++) {
                uint32_t A[2][4], B[2][4];
                LDSM4(A[0][0], A[0][1], A[0][2], A[0][3],
                      abase + xsw(mw * 32 + a_row,      kk * 32 + a_kb));
                LDSM4(A[1][0], A[1][1], A[1][2], A[1][3],
                      abase + xsw(mw * 32 + 16 + a_row, kk * 32 + a_kb));
                LDSM4(B[0][0], B[0][1], B[0][2], B[0][3],
                      bbase + xsw(nw * 32 + b_row,      kk * 32 + b_kb));
                LDSM4(B[1][0], B[1][1], B[1][2], B[1][3],
                      bbase + xsw(nw * 32 + 16 + b_row, kk * 32 + b_kb));
                #pragma unroll
                for (int mb = 0; mb < 2; mb++)
                    #pragma unroll
                    for (int pr = 0; pr < 2; pr++) {
                        mma_bf16(d1[mb][pr * 2 + 0], A[mb], &B[pr][0]);
                        mma_bf16(d1[mb][pr * 2 + 1], A[mb], &B[pr][2]);
                    }
            }
        }

        // ---- epilogue 1: tanh + split -> H ----
        #pragma unroll
        for (int mb = 0; mb < 2; mb++)
            #pragma unroll
            for (int nc = 0; nc < 4; nc++) {
                int c  = nw * 32 + nc * 8 + ec;
                int r0 = mw * 32 + mb * 16 + eg;
                float* dd = d1[mb][nc];
                uint32_t hi, lo;
                float v0 = ftanh(dd[0] + b1s[c]);
                float v1 = ftanh(dd[1] + b1s[c + 1]);
                split2(v0, v1, hi, lo);
                uint32_t o = hsw(r0, c * 2);
                *(uint32_t*)(smp + HHI_OFF + o) = hi;
                *(uint32_t*)(smp + HLO_OFF + o) = lo;
                float v2 = ftanh(dd[2] + b1s[c]);
                float v3 = ftanh(dd[3] + b1s[c + 1]);
                split2(v2, v3, hi, lo);
                o = hsw(r0 + 8, c * 2);
                *(uint32_t*)(smp + HHI_OFF + o) = hi;
                *(uint32_t*)(smp + HLO_OFF + o) = lo;
            }
        // warps reading H rows mw*32..+31 only need the writers with same mw
        asm volatile("bar.sync %0, %1;" :: "r"(1 + mw), "r"(128) : "memory");

        // ---- layer 2 GEMM: 3 split products, K=128 ----
        float d2[2][4][4];
        #pragma unroll
        for (int a = 0; a < 2; a++)
            #pragma unroll
            for (int b = 0; b < 4; b++)
                #pragma unroll
                for (int c = 0; c < 4; c++) d2[a][b][c] = 0.0f;

        #pragma unroll
        for (int p = 0; p < 3; p++) {
            const uint32_t abase = su + ((p == 2) ? HLO_OFF : HHI_OFF);
            const uint32_t bbase = su + ((p == 1) ? W2LO_OFF : W2HI_OFF);
            #pragma unroll
            for (int kk = 0; kk < 8; kk++) {
                uint32_t A[2][4], B[2][4];
                LDSM4(A[0][0], A[0][1], A[0][2], A[0][3],
                      abase + hsw(mw * 32 + a_row,      kk * 32 + a_kb));
                LDSM4(A[1][0], A[1][1], A[1][2], A[1][3],
                      abase + hsw(mw * 32 + 16 + a_row, kk * 32 + a_kb));
                LDSM4(B[0][0], B[0][1], B[0][2], B[0][3],
                      bbase + hsw(nw * 32 + b_row,      kk * 32 + b_kb));
                LDSM4(B[1][0], B[1][1], B[1][2], B[1][3],
                      bbase + hsw(nw * 32 + 16 + b_row, kk * 32 + b_kb));
                #pragma unroll
                for (int mb = 0; mb < 2; mb++)
                    #pragma unroll
                    for (int pr = 0; pr < 2; pr++) {
                        mma_bf16(d2[mb][pr * 2 + 0], A[mb], &B[pr][0]);
                        mma_bf16(d2[mb][pr * 2 + 1], A[mb], &B[pr][2]);
                    }
            }
        }

        // ---- epilogue 2: tanh, dot with W3, reduce ----
        {
            float pr[2][2];
            pr[0][0] = pr[0][1] = pr[1][0] = pr[1][1] = 0.0f;
            #pragma unroll
            for (int mb = 0; mb < 2; mb++)
                #pragma unroll
                for (int nc = 0; nc < 4; nc++) {
                    int c = nw * 32 + nc * 8 + ec;
                    float* dd = d2[mb][nc];
                    float w0 = W3s[c], w1 = W3s[c + 1];
                    float bb0 = b2s[c], bb1 = b2s[c + 1];
                    pr[mb][0] += ftanh(dd[0] + bb0) * w0 + ftanh(dd[1] + bb1) * w1;
                    pr[mb][1] += ftanh(dd[2] + bb0) * w0 + ftanh(dd[3] + bb1) * w1;
                }
            #pragma unroll
            for (int mb = 0; mb < 2; mb++)
                #pragma unroll
                for (int h = 0; h < 2; h++) {
                    pr[mb][h] += __shfl_xor_sync(0xffffffffu, pr[mb][h], 1);
                    pr[mb][h] += __shfl_xor_sync(0xffffffffu, pr[mb][h], 2);
                }
            if ((lane & 3) == 0) {
                #pragma unroll
                for (int mb = 0; mb < 2; mb++) {
                    int r0 = mw * 32 + mb * 16 + eg;
                    pps[nw * 128 + r0]     = pr[mb][0];
                    pps[nw * 128 + r0 + 8] = pr[mb][1];
                }
            }
        }
        __syncthreads();

        // ---- finalize: sum over nw groups, layer-3 tanh, AR term ----
        if (tid < 128) {
            const int s = tid;
            float pv = pps[s] + pps[128 + s] + pps[256 + s] + pps[384 + s];
            float ar = 0.0f;
            if (add_ar) {
                #pragma unroll
                for (int j = 0; j < 32; j++) {
                    uint32_t o = xsw(s, j * 4);
                    __nv_bfloat162 h = *(__nv_bfloat162*)(smp + XHI_OFF + o);
                    __nv_bfloat162 l = *(__nv_bfloat162*)(smp + XLO_OFF + o);
                    float x0 = __bfloat162float(h.x) + __bfloat162float(l.x);
                    float x1 = __bfloat162float(h.y) + __bfloat162float(l.y);
                    ar = fmaf(x0, ags[2 * j], fmaf(x1, ags[2 * j + 1], ar));
                }
            }
            outp[base + s] = ftanh(pv + b3v) * max_os + ar;
        }
        __syncthreads();
    }
}

// ---------------------------------------------------------------------------
__global__ void stencil_kernel(const float* __restrict__ xnn,
                               const float* __restrict__ sigma_l,
                               float* __restrict__ outp)
{
    int i = blockIdx.x * blockDim.x + threadIdx.x;
    if (i >= NSITE) return;
    int b = i & 15;
    int z = (i >> 4) & 31;
    int y = (i >> 9) & 31;
    int x = (i >> 14) & 31;
    int xm = (x + 31) & 31, xp = (x + 1) & 31;
    int ym = (y + 31) & 31, yp = (y + 1) & 31;
    int zm = (z + 31) & 31, zp = (z + 1) & 31;

    #define SIDX(X, Y, Z, B) ((((((X) << 5) + (Y)) << 5) + (Z)) * 16 + (B))
    float s = xnn[SIDX(xm, y, zm, b)] + xnn[SIDX(xm, y, zp, b)]
            + xnn[SIDX(xp, y, zm, b)] + xnn[SIDX(xp, y, zp, b)]
            + xnn[SIDX(x, ym, zm, b)] + xnn[SIDX(x, ym, zp, b)]
            + xnn[SIDX(x, yp, zm, b)] + xnn[SIDX(x, yp, zp, b)];
    #undef SIDX

    outp[i] = outp[i] + s * 0.125f;
    outp[NSITE + i] = expf(sigma_l[0]);
}

// ---------------------------------------------------------------------------
extern "C" void kernel_launch(void* const* d_in, const int* in_sizes, int n_in,
                              void* d_out, int out_size)
{
    const float* x_in    = (const float*)d_in[0];
    const float* weight  = (const float*)d_in[1];
    const float* ag      = (const float*)d_in[2];
    const float* W1      = (const float*)d_in[3];
    const float* b1      = (const float*)d_in[4];
    const float* W2      = (const float*)d_in[5];
    const float* b2      = (const float*)d_in[6];
    const float* W3      = (const float*)d_in[7];
    const float* b3      = (const float*)d_in[8];
    const float* W1n     = (const float*)d_in[9];
    const float* b1n     = (const float*)d_in[10];
    const float* W2n     = (const float*)d_in[11];
    const float* b2n     = (const float*)d_in[12];
    const float* W3n     = (const float*)d_in[13];
    const float* b3n     = (const float*)d_in[14];
    const float* max_osl = (const float*)d_in[15];
    const float* sigmal  = (const float*)d_in[16];
    float* out = (float*)d_out;

    cudaFuncSetAttribute(mlp_tc_kernel,
                         cudaFuncAttributeMaxDynamicSharedMemorySize, SMEM_BYTES);

    float* xnn;
    cudaGetSymbolAddress((void**)&xnn, g_xnn);

    mlp_tc_kernel<<<GRID, NTHR, SMEM_BYTES>>>(x_in, weight, W1, b1, W2, b2, W3, b3,
                                              ag, max_osl, out, 1);
    mlp_tc_kernel<<<GRID, NTHR, SMEM_BYTES>>>(x_in, weight, W1n, b1n, W2n, b2n, W3n, b3n,
                                              ag, max_osl, xnn, 0);
    stencil_kernel<<<(NSITE + 255) / 256, 256>>>(xnn, sigmal, out);
}

// round 5
// speedup vs baseline: 3.5809x; 1.4702x over previous
#include <cuda_runtime.h>
#include <cuda_bf16.h>
#include <math.h>
#include <stdint.h>

#define NSITE  524288          // 32*32*32*16
#define TILE   128
#define NTILES 4096
#define GRID   148
#define NTHR   512

// ---- dynamic smem layout (bytes) ----
#define XHI_OFF    0           // [128 sites x 64 bf16] 128B rows, swizzled
#define XLO_OFF    16384
#define W1HI_OFF   32768       // [128 n x 64 k bf16]
#define W1LO_OFF   49152
#define W2HI_OFF   65536       // [128 n x 128 k bf16] blocked atoms
#define W2LO_OFF   98304
#define HHI_OFF    131072      // [128 sites x 128 mid bf16] blocked atoms
#define HLO_OFF    163840
#define B1S_OFF    196608
#define B2S_OFF    197120
#define W3S_OFF    197632
#define AGS_OFF    198144
#define PPS_OFF    198400      // 4*128 f32
#define SMEM_BYTES 200448

// swizzle: XOR bits[4:6] with bits[7:9] (conflict-free ldmatrix on 128B rows)
__device__ __forceinline__ uint32_t swz(uint32_t o) { return o ^ ((o >> 3) & 0x70); }
// 128B-row tiles (X, W1): row 0..127, colb = byte within row (0..127)
__device__ __forceinline__ uint32_t xsw(int row, int colb) {
    return swz((uint32_t)(row * 128 + colb));
}
// 256B-row tiles (H, W2) in blocked atoms: atom = (row/8) + (colb/128)*16
__device__ __forceinline__ uint32_t hsw(int row, int colb) {
    uint32_t o = (uint32_t)((((row >> 3) + (colb >> 7) * 16) << 10)
                            + ((row & 7) << 7) + (colb & 127));
    return swz(o);
}

__device__ __forceinline__ void split2(float a, float b, uint32_t& hi, uint32_t& lo) {
    __nv_bfloat162 h, l;
    h.x = __float2bfloat16_rn(a);
    h.y = __float2bfloat16_rn(b);
    l.x = __float2bfloat16_rn(a - __bfloat162float(h.x));
    l.y = __float2bfloat16_rn(b - __bfloat162float(h.y));
    hi = reinterpret_cast<uint32_t&>(h);
    lo = reinterpret_cast<uint32_t&>(l);
}

// tanh via 2 MUFU (ex2 + rcp), abs err ~2e-7
__device__ __forceinline__ float ftanh(float x) {
    float t = __expf(2.0f * x);
    return 1.0f - __fdividef(2.0f, 1.0f + t);
}

#define LDSM4(r, a) \
    asm volatile("ldmatrix.sync.aligned.m8n8.x4.shared.b16 {%0,%1,%2,%3}, [%4];" \
                 : "=r"((r)[0]), "=r"((r)[1]), "=r"((r)[2]), "=r"((r)[3]) : "r"(a))

__device__ __forceinline__ void mma_bf16(float* d, const uint32_t* a, const uint32_t* b) {
    asm volatile(
        "mma.sync.aligned.m16n8k16.row.col.f32.bf16.bf16.f32 "
        "{%0,%1,%2,%3},{%4,%5,%6,%7},{%8,%9},{%0,%1,%2,%3};"
        : "+f"(d[0]), "+f"(d[1]), "+f"(d[2]), "+f"(d[3])
        : "r"(a[0]), "r"(a[1]), "r"(a[2]), "r"(a[3]), "r"(b[0]), "r"(b[1]));
}

__device__ float g_xnn[NSITE];

// ---------------------------------------------------------------------------
__global__ __launch_bounds__(NTHR, 1)
void mlp_tc_kernel(const float* __restrict__ xg,
                   const float* __restrict__ weight,
                   const float* __restrict__ W1, const float* __restrict__ b1,
                   const float* __restrict__ W2, const float* __restrict__ b2,
                   const float* __restrict__ W3, const float* __restrict__ b3,
                   const float* __restrict__ ag,
                   const float* __restrict__ max_os_l,
                   float* __restrict__ outp,
                   int add_ar)
{
    extern __shared__ char smp[];
    uint32_t su;
    asm("{ .reg .u64 t; cvta.to.shared.u64 t, %1; cvt.u32.u64 %0, t; }"
        : "=r"(su) : "l"(smp));

    const int tid  = threadIdx.x;
    const int wid  = tid >> 5;
    const int lane = tid & 31;
    const int mw   = wid & 3;     // M block of 32 sites
    const int nw   = wid >> 2;    // N block of 32 outputs

    // ldmatrix lane geometry
    const int lm = lane >> 3;     // matrix id 0..3
    const int lr = lane & 7;      // row within matrix
    const int a_row = ((lm & 1) << 3) + lr;
    const int a_kb  = (lm >> 1) << 4;
    const int b_row = ((lm >> 1) << 3) + lr;
    const int b_kb  = (lm & 1) << 4;
    // epilogue geometry
    const int eg = lane >> 2;          // row group 0..7
    const int ec = (lane & 3) << 1;    // col pair base 0,2,4,6

    float* b1s = (float*)(smp + B1S_OFF);
    float* b2s = (float*)(smp + B2S_OFF);
    float* W3s = (float*)(smp + W3S_OFF);
    float* ags = (float*)(smp + AGS_OFF);
    float* pps = (float*)(smp + PPS_OFF);

    // ---- one-time weight prep (split bf16) ----
    for (int idx = tid; idx < 128 * 32; idx += NTHR) {     // W1 (weight folded in)
        int n = idx >> 5, j = idx & 31;
        float w0 = W1[n * 64 + 2 * j]     * weight[2 * j];
        float w1 = W1[n * 64 + 2 * j + 1] * weight[2 * j + 1];
        uint32_t hi, lo; split2(w0, w1, hi, lo);
        uint32_t o = xsw(n, j * 4);
        *(uint32_t*)(smp + W1HI_OFF + o) = hi;
        *(uint32_t*)(smp + W1LO_OFF + o) = lo;
    }
    for (int idx = tid; idx < 128 * 64; idx += NTHR) {     // W2
        int n = idx >> 6, j = idx & 63;
        float w0 = W2[n * 128 + 2 * j];
        float w1 = W2[n * 128 + 2 * j + 1];
        uint32_t hi, lo; split2(w0, w1, hi, lo);
        uint32_t o = hsw(n, j * 4);
        *(uint32_t*)(smp + W2HI_OFF + o) = hi;
        *(uint32_t*)(smp + W2LO_OFF + o) = lo;
    }
    if (tid < 128) { b1s[tid] = b1[tid]; b2s[tid] = b2[tid]; W3s[tid] = W3[tid]; }
    if (tid < 64)  ags[tid] = add_ar ? ag[tid] : 0.0f;

    const float max_os = expf(max_os_l[0]);
    const float b3v    = b3[0];
    __syncthreads();

    // per-thread staging coordinates (8 float2 per thread per tile)
    const int sx = tid >> 5;          // site row base pattern: s = sx + it*16
    const int sj = tid & 31;          // float2 column

    // ---- prefetch first tile into registers ----
    float2 v[8];
    {
        int t0 = blockIdx.x;
        if (t0 < NTILES) {
            const float2* xg2 = (const float2*)(xg + (size_t)t0 * TILE * 64);
            #pragma unroll
            for (int it = 0; it < 8; it++)
                v[it] = xg2[(sx + it * 16) * 32 + sj];
        }
    }

    for (int tile = blockIdx.x; tile < NTILES; tile += gridDim.x) {
        const int base = tile * TILE;

        // ---- stage X tile from registers: fp32 -> split bf16 ----
        #pragma unroll
        for (int it = 0; it < 8; it++) {
            int s = sx + it * 16;
            uint32_t hi, lo; split2(v[it].x, v[it].y, hi, lo);
            uint32_t o = xsw(s, sj * 4);
            *(uint32_t*)(smp + XHI_OFF + o) = hi;
            *(uint32_t*)(smp + XLO_OFF + o) = lo;
        }
        __syncthreads();

        // ---- prefetch next tile (drains behind the two GEMMs) ----
        {
            int nt = tile + gridDim.x;
            if (nt < NTILES) {
                const float2* xg2 = (const float2*)(xg + (size_t)nt * TILE * 64);
                #pragma unroll
                for (int it = 0; it < 8; it++)
                    v[it] = xg2[(sx + it * 16) * 32 + sj];
            }
        }

        // ---- layer 1 GEMM: shared fragments, 3 split products, K=64 ----
        float d1[2][4][4];
        #pragma unroll
        for (int a = 0; a < 2; a++)
            #pragma unroll
            for (int b = 0; b < 4; b++)
                #pragma unroll
                for (int c = 0; c < 4; c++) d1[a][b][c] = 0.0f;

        #pragma unroll
        for (int kk = 0; kk < 4; kk++) {
            uint32_t Ah[2][4], Al[2][4], Bh[2][4], Bl[2][4];
            LDSM4(Ah[0], su + XHI_OFF  + xsw(mw * 32 + a_row,      kk * 32 + a_kb));
            LDSM4(Ah[1], su + XHI_OFF  + xsw(mw * 32 + 16 + a_row, kk * 32 + a_kb));
            LDSM4(Al[0], su + XLO_OFF  + xsw(mw * 32 + a_row,      kk * 32 + a_kb));
            LDSM4(Al[1], su + XLO_OFF  + xsw(mw * 32 + 16 + a_row, kk * 32 + a_kb));
            LDSM4(Bh[0], su + W1HI_OFF + xsw(nw * 32 + b_row,      kk * 32 + b_kb));
            LDSM4(Bh[1], su + W1HI_OFF + xsw(nw * 32 + 16 + b_row, kk * 32 + b_kb));
            LDSM4(Bl[0], su + W1LO_OFF + xsw(nw * 32 + b_row,      kk * 32 + b_kb));
            LDSM4(Bl[1], su + W1LO_OFF + xsw(nw * 32 + 16 + b_row, kk * 32 + b_kb));
            #pragma unroll
            for (int mb = 0; mb < 2; mb++)
                #pragma unroll
                for (int pr = 0; pr < 2; pr++) {
                    mma_bf16(d1[mb][pr * 2 + 0], Ah[mb], &Bh[pr][0]);
                    mma_bf16(d1[mb][pr * 2 + 1], Ah[mb], &Bh[pr][2]);
                    mma_bf16(d1[mb][pr * 2 + 0], Ah[mb], &Bl[pr][0]);
                    mma_bf16(d1[mb][pr * 2 + 1], Ah[mb], &Bl[pr][2]);
                    mma_bf16(d1[mb][pr * 2 + 0], Al[mb], &Bh[pr][0]);
                    mma_bf16(d1[mb][pr * 2 + 1], Al[mb], &Bh[pr][2]);
                }
        }

        // ---- epilogue 1: tanh + split -> H ----
        #pragma unroll
        for (int mb = 0; mb < 2; mb++)
            #pragma unroll
            for (int nc = 0; nc < 4; nc++) {
                int c  = nw * 32 + nc * 8 + ec;
                int r0 = mw * 32 + mb * 16 + eg;
                float* dd = d1[mb][nc];
                uint32_t hi, lo;
                float v0 = ftanh(dd[0] + b1s[c]);
                float v1 = ftanh(dd[1] + b1s[c + 1]);
                split2(v0, v1, hi, lo);
                uint32_t o = hsw(r0, c * 2);
                *(uint32_t*)(smp + HHI_OFF + o) = hi;
                *(uint32_t*)(smp + HLO_OFF + o) = lo;
                float v2 = ftanh(dd[2] + b1s[c]);
                float v3 = ftanh(dd[3] + b1s[c + 1]);
                split2(v2, v3, hi, lo);
                o = hsw(r0 + 8, c * 2);
                *(uint32_t*)(smp + HHI_OFF + o) = hi;
                *(uint32_t*)(smp + HLO_OFF + o) = lo;
            }
        // warps reading H rows mw*32..+31 only need the writers with same mw
        asm volatile("bar.sync %0, %1;" :: "r"(1 + mw), "r"(128) : "memory");

        // ---- layer 2 GEMM: shared fragments, 3 split products, K=128 ----
        float d2[2][4][4];
        #pragma unroll
        for (int a = 0; a < 2; a++)
            #pragma unroll
            for (int b = 0; b < 4; b++)
                #pragma unroll
                for (int c = 0; c < 4; c++) d2[a][b][c] = 0.0f;

        #pragma unroll
        for (int kk = 0; kk < 8; kk++) {
            uint32_t Ah[2][4], Al[2][4], Bh[2][4], Bl[2][4];
            LDSM4(Ah[0], su + HHI_OFF  + hsw(mw * 32 + a_row,      kk * 32 + a_kb));
            LDSM4(Ah[1], su + HHI_OFF  + hsw(mw * 32 + 16 + a_row, kk * 32 + a_kb));
            LDSM4(Al[0], su + HLO_OFF  + hsw(mw * 32 + a_row,      kk * 32 + a_kb));
            LDSM4(Al[1], su + HLO_OFF  + hsw(mw * 32 + 16 + a_row, kk * 32 + a_kb));
            LDSM4(Bh[0], su + W2HI_OFF + hsw(nw * 32 + b_row,      kk * 32 + b_kb));
            LDSM4(Bh[1], su + W2HI_OFF + hsw(nw * 32 + 16 + b_row, kk * 32 + b_kb));
            LDSM4(Bl[0], su + W2LO_OFF + hsw(nw * 32 + b_row,      kk * 32 + b_kb));
            LDSM4(Bl[1], su + W2LO_OFF + hsw(nw * 32 + 16 + b_row, kk * 32 + b_kb));
            #pragma unroll
            for (int mb = 0; mb < 2; mb++)
                #pragma unroll
                for (int pr = 0; pr < 2; pr++) {
                    mma_bf16(d2[mb][pr * 2 + 0], Ah[mb], &Bh[pr][0]);
                    mma_bf16(d2[mb][pr * 2 + 1], Ah[mb], &Bh[pr][2]);
                    mma_bf16(d2[mb][pr * 2 + 0], Ah[mb], &Bl[pr][0]);
                    mma_bf16(d2[mb][pr * 2 + 1], Ah[mb], &Bl[pr][2]);
                    mma_bf16(d2[mb][pr * 2 + 0], Al[mb], &Bh[pr][0]);
                    mma_bf16(d2[mb][pr * 2 + 1], Al[mb], &Bh[pr][2]);
                }
        }

        // ---- epilogue 2: tanh, dot with W3, reduce ----
        {
            float pr[2][2];
            pr[0][0] = pr[0][1] = pr[1][0] = pr[1][1] = 0.0f;
            #pragma unroll
            for (int mb = 0; mb < 2; mb++)
                #pragma unroll
                for (int nc = 0; nc < 4; nc++) {
                    int c = nw * 32 + nc * 8 + ec;
                    float* dd = d2[mb][nc];
                    float w0 = W3s[c], w1 = W3s[c + 1];
                    float bb0 = b2s[c], bb1 = b2s[c + 1];
                    pr[mb][0] += ftanh(dd[0] + bb0) * w0 + ftanh(dd[1] + bb1) * w1;
                    pr[mb][1] += ftanh(dd[2] + bb0) * w0 + ftanh(dd[3] + bb1) * w1;
                }
            #pragma unroll
            for (int mb = 0; mb < 2; mb++)
                #pragma unroll
                for (int h = 0; h < 2; h++) {
                    pr[mb][h] += __shfl_xor_sync(0xffffffffu, pr[mb][h], 1);
                    pr[mb][h] += __shfl_xor_sync(0xffffffffu, pr[mb][h], 2);
                }
            if ((lane & 3) == 0) {
                #pragma unroll
                for (int mb = 0; mb < 2; mb++) {
                    int r0 = mw * 32 + mb * 16 + eg;
                    pps[nw * 128 + r0]     = pr[mb][0];
                    pps[nw * 128 + r0 + 8] = pr[mb][1];
                }
            }
        }
        __syncthreads();

        // ---- finalize: sum over nw groups, layer-3 tanh, AR term ----
        if (tid < 128) {
            const int s = tid;
            float pv = pps[s] + pps[128 + s] + pps[256 + s] + pps[384 + s];
            float ar = 0.0f;
            if (add_ar) {
                #pragma unroll
                for (int j = 0; j < 32; j++) {
                    uint32_t o = xsw(s, j * 4);
                    __nv_bfloat162 h = *(__nv_bfloat162*)(smp + XHI_OFF + o);
                    __nv_bfloat162 l = *(__nv_bfloat162*)(smp + XLO_OFF + o);
                    float x0 = __bfloat162float(h.x) + __bfloat162float(l.x);
                    float x1 = __bfloat162float(h.y) + __bfloat162float(l.y);
                    ar = fmaf(x0, ags[2 * j], fmaf(x1, ags[2 * j + 1], ar));
                }
            }
            outp[base + s] = ftanh(pv + b3v) * max_os + ar;
        }
        __syncthreads();
    }
}

// ---------------------------------------------------------------------------
__global__ void stencil_kernel(const float* __restrict__ xnn,
                               const float* __restrict__ sigma_l,
                               float* __restrict__ outp)
{
    int i = blockIdx.x * blockDim.x + threadIdx.x;
    if (i >= NSITE) return;
    int b = i & 15;
    int z = (i >> 4) & 31;
    int y = (i >> 9) & 31;
    int x = (i >> 14) & 31;
    int xm = (x + 31) & 31, xp = (x + 1) & 31;
    int ym = (y + 31) & 31, yp = (y + 1) & 31;
    int zm = (z + 31) & 31, zp = (z + 1) & 31;

    #define SIDX(X, Y, Z, B) ((((((X) << 5) + (Y)) << 5) + (Z)) * 16 + (B))
    float s = xnn[SIDX(xm, y, zm, b)] + xnn[SIDX(xm, y, zp, b)]
            + xnn[SIDX(xp, y, zm, b)] + xnn[SIDX(xp, y, zp, b)]
            + xnn[SIDX(x, ym, zm, b)] + xnn[SIDX(x, ym, zp, b)]
            + xnn[SIDX(x, yp, zm, b)] + xnn[SIDX(x, yp, zp, b)];
    #undef SIDX

    outp[i] = outp[i] + s * 0.125f;
    outp[NSITE + i] = expf(sigma_l[0]);
}

// ---------------------------------------------------------------------------
extern "C" void kernel_launch(void* const* d_in, const int* in_sizes, int n_in,
                              void* d_out, int out_size)
{
    const float* x_in    = (const float*)d_in[0];
    const float* weight  = (const float*)d_in[1];
    const float* ag      = (const float*)d_in[2];
    const float* W1      = (const float*)d_in[3];
    const float* b1      = (const float*)d_in[4];
    const float* W2      = (const float*)d_in[5];
    const float* b2      = (const float*)d_in[6];
    const float* W3      = (const float*)d_in[7];
    const float* b3      = (const float*)d_in[8];
    const float* W1n     = (const float*)d_in[9];
    const float* b1n     = (const float*)d_in[10];
    const float* W2n     = (const float*)d_in[11];
    const float* b2n     = (const float*)d_in[12];
    const float* W3n     = (const float*)d_in[13];
    const float* b3n     = (const float*)d_in[14];
    const float* max_osl = (const float*)d_in[15];
    const float* sigmal  = (const float*)d_in[16];
    float* out = (float*)d_out;

    cudaFuncSetAttribute(mlp_tc_kernel,
                         cudaFuncAttributeMaxDynamicSharedMemorySize, SMEM_BYTES);

    float* xnn;
    cudaGetSymbolAddress((void**)&xnn, g_xnn);

    mlp_tc_kernel<<<GRID, NTHR, SMEM_BYTES>>>(x_in, weight, W1, b1, W2, b2, W3, b3,
                                              ag, max_osl, out, 1);
    mlp_tc_kernel<<<GRID, NTHR, SMEM_BYTES>>>(x_in, weight, W1n, b1n, W2n, b2n, W3n, b3n,
                                              ag, max_osl, xnn, 0);
    stencil_kernel<<<(NSITE + 255) / 256, 256>>>(xnn, sigmal, out);
}

// round 6
// speedup vs baseline: 3.7968x; 1.0603x over previous
#include <cuda_runtime.h>
#include <cuda_bf16.h>
#include <math.h>
#include <stdint.h>

#define NSITE  524288          // 32*32*32*16
#define TILE   128
#define NTILES 4096
#define GRID   148
#define NTHR   512

// ---- dynamic smem layout (bytes) ----
#define XHI_OFF    0           // [128 sites x 64 bf16] 128B rows, swizzled
#define XLO_OFF    16384
#define W1HI_OFF   32768       // [128 n x 64 k bf16]
#define W1LO_OFF   49152
#define W2HI_OFF   65536       // [128 n x 128 k bf16] blocked atoms
#define W2LO_OFF   98304
#define HHI_OFF    131072      // [128 sites x 128 mid bf16] blocked atoms
#define HLO_OFF    163840
#define B1S_OFF    196608
#define B2S_OFF    197120
#define W3S_OFF    197632
#define AGS_OFF    198144
#define PPS_OFF    198400      // 4*128 f32
#define SMEM_BYTES 200448

// swizzle: XOR bits[4:6] with bits[7:9] (conflict-free ldmatrix on 128B rows)
__device__ __forceinline__ uint32_t swz(uint32_t o) { return o ^ ((o >> 3) & 0x70); }
// 128B-row tiles (X, W1): row 0..127, colb = byte within row (0..127)
__device__ __forceinline__ uint32_t xsw(int row, int colb) {
    return swz((uint32_t)(row * 128 + colb));
}
// 256B-row tiles (H, W2) in blocked atoms: atom = (row/8) + (colb/128)*16
__device__ __forceinline__ uint32_t hsw(int row, int colb) {
    uint32_t o = (uint32_t)((((row >> 3) + (colb >> 7) * 16) << 10)
                            + ((row & 7) << 7) + (colb & 127));
    return swz(o);
}

__device__ __forceinline__ void split2(float a, float b, uint32_t& hi, uint32_t& lo) {
    __nv_bfloat162 h, l;
    h.x = __float2bfloat16_rn(a);
    h.y = __float2bfloat16_rn(b);
    l.x = __float2bfloat16_rn(a - __bfloat162float(h.x));
    l.y = __float2bfloat16_rn(b - __bfloat162float(h.y));
    hi = reinterpret_cast<uint32_t&>(h);
    lo = reinterpret_cast<uint32_t&>(l);
}

// tanh via 2 MUFU (ex2 + rcp), abs err ~2e-7
__device__ __forceinline__ float ftanh(float x) {
    float t = __expf(2.0f * x);
    return 1.0f - __fdividef(2.0f, 1.0f + t);
}

#define LDSM4(r, a) \
    asm volatile("ldmatrix.sync.aligned.m8n8.x4.shared.b16 {%0,%1,%2,%3}, [%4];" \
                 : "=r"((r)[0]), "=r"((r)[1]), "=r"((r)[2]), "=r"((r)[3]) : "r"(a))

__device__ __forceinline__ void mma_bf16(float* d, const uint32_t* a, const uint32_t* b) {
    asm volatile(
        "mma.sync.aligned.m16n8k16.row.col.f32.bf16.bf16.f32 "
        "{%0,%1,%2,%3},{%4,%5,%6,%7},{%8,%9},{%0,%1,%2,%3};"
        : "+f"(d[0]), "+f"(d[1]), "+f"(d[2]), "+f"(d[3])
        : "r"(a[0]), "r"(a[1]), "r"(a[2]), "r"(a[3]), "r"(b[0]), "r"(b[1]));
}

// per-group barrier: 4 warps (one per SMSP), IDs 1..4
#define BARG() asm volatile("bar.sync %0, 128;" :: "r"(1 + mw) : "memory")

__device__ float g_xnn[NSITE];

// ---------------------------------------------------------------------------
__global__ __launch_bounds__(NTHR, 1)
void mlp_tc_kernel(const float* __restrict__ xg,
                   const float* __restrict__ weight,
                   const float* __restrict__ W1, const float* __restrict__ b1,
                   const float* __restrict__ W2, const float* __restrict__ b2,
                   const float* __restrict__ W3, const float* __restrict__ b3,
                   const float* __restrict__ ag,
                   const float* __restrict__ max_os_l,
                   float* __restrict__ outp,
                   int add_ar)
{
    extern __shared__ char smp[];
    uint32_t su;
    asm("{ .reg .u64 t; cvta.to.shared.u64 t, %1; cvt.u32.u64 %0, t; }"
        : "=r"(su) : "l"(smp));

    const int tid  = threadIdx.x;
    const int wid  = tid >> 5;
    const int lane = tid & 31;
    // group decomposition: group mw owns sites mw*32..mw*32+31 of each tile.
    // warps of a group sit on the 4 different SMSPs -> phase drift between
    // groups overlaps tensor(GEMM) with MUFU(epilogue) on every scheduler.
    const int mw   = wid >> 2;    // group / M block of 32 sites
    const int nw   = wid & 3;     // N block of 32 outputs within group
    const int wtid = nw * 32 + lane;  // 0..127 within group

    // ldmatrix lane geometry
    const int lm = lane >> 3;
    const int lr = lane & 7;
    const int a_row = ((lm & 1) << 3) + lr;
    const int a_kb  = (lm >> 1) << 4;
    const int b_row = ((lm >> 1) << 3) + lr;
    const int b_kb  = (lm & 1) << 4;
    // epilogue geometry
    const int eg = lane >> 2;
    const int ec = (lane & 3) << 1;

    float* b1s = (float*)(smp + B1S_OFF);
    float* b2s = (float*)(smp + B2S_OFF);
    float* W3s = (float*)(smp + W3S_OFF);
    float* ags = (float*)(smp + AGS_OFF);
    float* pps = (float*)(smp + PPS_OFF);

    // ---- one-time weight prep (split bf16) ----
    for (int idx = tid; idx < 128 * 32; idx += NTHR) {     // W1 (weight folded in)
        int n = idx >> 5, j = idx & 31;
        float w0 = W1[n * 64 + 2 * j]     * weight[2 * j];
        float w1 = W1[n * 64 + 2 * j + 1] * weight[2 * j + 1];
        uint32_t hi, lo; split2(w0, w1, hi, lo);
        uint32_t o = xsw(n, j * 4);
        *(uint32_t*)(smp + W1HI_OFF + o) = hi;
        *(uint32_t*)(smp + W1LO_OFF + o) = lo;
    }
    for (int idx = tid; idx < 128 * 64; idx += NTHR) {     // W2
        int n = idx >> 6, j = idx & 63;
        float w0 = W2[n * 128 + 2 * j];
        float w1 = W2[n * 128 + 2 * j + 1];
        uint32_t hi, lo; split2(w0, w1, hi, lo);
        uint32_t o = hsw(n, j * 4);
        *(uint32_t*)(smp + W2HI_OFF + o) = hi;
        *(uint32_t*)(smp + W2LO_OFF + o) = lo;
    }
    if (tid < 128) { b1s[tid] = b1[tid]; b2s[tid] = b2[tid]; W3s[tid] = W3[tid]; }
    if (tid < 64)  ags[tid] = add_ar ? ag[tid] : 0.0f;

    const float max_os = expf(max_os_l[0]);
    const float b3v    = b3[0];
    __syncthreads();

    // intra-group staging coordinates: 4 float4 per thread per tile
    const int s_row = mw * 32 + (wtid >> 2);  // tile row this thread stages
    const int s_f4  = wtid & 3;               // float4 column base

    // ---- prefetch first tile into registers ----
    float4 v[4];
    {
        int t0 = blockIdx.x;
        if (t0 < NTILES) {
            const float4* xg4 = (const float4*)(xg + (size_t)t0 * TILE * 64);
            #pragma unroll
            for (int it = 0; it < 4; it++)
                v[it] = xg4[s_row * 16 + s_f4 + it * 4];
        }
    }

    for (int tile = blockIdx.x; tile < NTILES; tile += gridDim.x) {
        const int base = tile * TILE;

        // ---- stage group's X rows from registers: fp32 -> split bf16 ----
        #pragma unroll
        for (int it = 0; it < 4; it++) {
            int f4 = s_f4 + it * 4;
            uint32_t hi, lo;
            split2(v[it].x, v[it].y, hi, lo);
            uint32_t o = xsw(s_row, f4 * 8);
            *(uint32_t*)(smp + XHI_OFF + o) = hi;
            *(uint32_t*)(smp + XLO_OFF + o) = lo;
            split2(v[it].z, v[it].w, hi, lo);
            o = xsw(s_row, f4 * 8 + 4);
            *(uint32_t*)(smp + XHI_OFF + o) = hi;
            *(uint32_t*)(smp + XLO_OFF + o) = lo;
        }
        BARG();

        // ---- prefetch next tile (drains behind the two GEMMs) ----
        {
            int nt = tile + gridDim.x;
            if (nt < NTILES) {
                const float4* xg4 = (const float4*)(xg + (size_t)nt * TILE * 64);
                #pragma unroll
                for (int it = 0; it < 4; it++)
                    v[it] = xg4[s_row * 16 + s_f4 + it * 4];
            }
        }

        // ---- layer 1 GEMM: shared fragments, 3 split products, K=64 ----
        float d1[2][4][4];
        #pragma unroll
        for (int a = 0; a < 2; a++)
            #pragma unroll
            for (int b = 0; b < 4; b++)
                #pragma unroll
                for (int c = 0; c < 4; c++) d1[a][b][c] = 0.0f;

        #pragma unroll
        for (int kk = 0; kk < 4; kk++) {
            uint32_t Ah[2][4], Al[2][4], Bh[2][4], Bl[2][4];
            LDSM4(Ah[0], su + XHI_OFF  + xsw(mw * 32 + a_row,      kk * 32 + a_kb));
            LDSM4(Ah[1], su + XHI_OFF  + xsw(mw * 32 + 16 + a_row, kk * 32 + a_kb));
            LDSM4(Al[0], su + XLO_OFF  + xsw(mw * 32 + a_row,      kk * 32 + a_kb));
            LDSM4(Al[1], su + XLO_OFF  + xsw(mw * 32 + 16 + a_row, kk * 32 + a_kb));
            LDSM4(Bh[0], su + W1HI_OFF + xsw(nw * 32 + b_row,      kk * 32 + b_kb));
            LDSM4(Bh[1], su + W1HI_OFF + xsw(nw * 32 + 16 + b_row, kk * 32 + b_kb));
            LDSM4(Bl[0], su + W1LO_OFF + xsw(nw * 32 + b_row,      kk * 32 + b_kb));
            LDSM4(Bl[1], su + W1LO_OFF + xsw(nw * 32 + 16 + b_row, kk * 32 + b_kb));
            #pragma unroll
            for (int mb = 0; mb < 2; mb++)
                #pragma unroll
                for (int pr = 0; pr < 2; pr++) {
                    mma_bf16(d1[mb][pr * 2 + 0], Ah[mb], &Bh[pr][0]);
                    mma_bf16(d1[mb][pr * 2 + 1], Ah[mb], &Bh[pr][2]);
                    mma_bf16(d1[mb][pr * 2 + 0], Ah[mb], &Bl[pr][0]);
                    mma_bf16(d1[mb][pr * 2 + 1], Ah[mb], &Bl[pr][2]);
                    mma_bf16(d1[mb][pr * 2 + 0], Al[mb], &Bh[pr][0]);
                    mma_bf16(d1[mb][pr * 2 + 1], Al[mb], &Bh[pr][2]);
                }
        }

        // ---- epilogue 1: tanh + split -> H (rows stay inside this group) ----
        #pragma unroll
        for (int mb = 0; mb < 2; mb++)
            #pragma unroll
            for (int nc = 0; nc < 4; nc++) {
                int c  = nw * 32 + nc * 8 + ec;
                int r0 = mw * 32 + mb * 16 + eg;
                float* dd = d1[mb][nc];
                uint32_t hi, lo;
                float v0 = ftanh(dd[0] + b1s[c]);
                float v1 = ftanh(dd[1] + b1s[c + 1]);
                split2(v0, v1, hi, lo);
                uint32_t o = hsw(r0, c * 2);
                *(uint32_t*)(smp + HHI_OFF + o) = hi;
                *(uint32_t*)(smp + HLO_OFF + o) = lo;
                float v2 = ftanh(dd[2] + b1s[c]);
                float v3 = ftanh(dd[3] + b1s[c + 1]);
                split2(v2, v3, hi, lo);
                o = hsw(r0 + 8, c * 2);
                *(uint32_t*)(smp + HHI_OFF + o) = hi;
                *(uint32_t*)(smp + HLO_OFF + o) = lo;
            }
        BARG();

        // ---- layer 2 GEMM: shared fragments, 3 split products, K=128 ----
        float d2[2][4][4];
        #pragma unroll
        for (int a = 0; a < 2; a++)
            #pragma unroll
            for (int b = 0; b < 4; b++)
                #pragma unroll
                for (int c = 0; c < 4; c++) d2[a][b][c] = 0.0f;

        #pragma unroll
        for (int kk = 0; kk < 8; kk++) {
            uint32_t Ah[2][4], Al[2][4], Bh[2][4], Bl[2][4];
            LDSM4(Ah[0], su + HHI_OFF  + hsw(mw * 32 + a_row,      kk * 32 + a_kb));
            LDSM4(Ah[1], su + HHI_OFF  + hsw(mw * 32 + 16 + a_row, kk * 32 + a_kb));
            LDSM4(Al[0], su + HLO_OFF  + hsw(mw * 32 + a_row,      kk * 32 + a_kb));
            LDSM4(Al[1], su + HLO_OFF  + hsw(mw * 32 + 16 + a_row, kk * 32 + a_kb));
            LDSM4(Bh[0], su + W2HI_OFF + hsw(nw * 32 + b_row,      kk * 32 + b_kb));
            LDSM4(Bh[1], su + W2HI_OFF + hsw(nw * 32 + 16 + b_row, kk * 32 + b_kb));
            LDSM4(Bl[0], su + W2LO_OFF + hsw(nw * 32 + b_row,      kk * 32 + b_kb));
            LDSM4(Bl[1], su + W2LO_OFF + hsw(nw * 32 + 16 + b_row, kk * 32 + b_kb));
            #pragma unroll
            for (int mb = 0; mb < 2; mb++)
                #pragma unroll
                for (int pr = 0; pr < 2; pr++) {
                    mma_bf16(d2[mb][pr * 2 + 0], Ah[mb], &Bh[pr][0]);
                    mma_bf16(d2[mb][pr * 2 + 1], Ah[mb], &Bh[pr][2]);
                    mma_bf16(d2[mb][pr * 2 + 0], Ah[mb], &Bl[pr][0]);
                    mma_bf16(d2[mb][pr * 2 + 1], Ah[mb], &Bl[pr][2]);
                    mma_bf16(d2[mb][pr * 2 + 0], Al[mb], &Bh[pr][0]);
                    mma_bf16(d2[mb][pr * 2 + 1], Al[mb], &Bh[pr][2]);
                }
        }

        // ---- epilogue 2: tanh, dot with W3, reduce -> pps ----
        {
            float pr[2][2];
            pr[0][0] = pr[0][1] = pr[1][0] = pr[1][1] = 0.0f;
            #pragma unroll
            for (int mb = 0; mb < 2; mb++)
                #pragma unroll
                for (int nc = 0; nc < 4; nc++) {
                    int c = nw * 32 + nc * 8 + ec;
                    float* dd = d2[mb][nc];
                    float w0 = W3s[c], w1 = W3s[c + 1];
                    float bb0 = b2s[c], bb1 = b2s[c + 1];
                    pr[mb][0] += ftanh(dd[0] + bb0) * w0 + ftanh(dd[1] + bb1) * w1;
                    pr[mb][1] += ftanh(dd[2] + bb0) * w0 + ftanh(dd[3] + bb1) * w1;
                }
            #pragma unroll
            for (int mb = 0; mb < 2; mb++)
                #pragma unroll
                for (int h = 0; h < 2; h++) {
                    pr[mb][h] += __shfl_xor_sync(0xffffffffu, pr[mb][h], 1);
                    pr[mb][h] += __shfl_xor_sync(0xffffffffu, pr[mb][h], 2);
                }
            if ((lane & 3) == 0) {
                #pragma unroll
                for (int mb = 0; mb < 2; mb++) {
                    int r0 = mw * 32 + mb * 16 + eg;
                    pps[nw * 128 + r0]     = pr[mb][0];
                    pps[nw * 128 + r0 + 8] = pr[mb][1];
                }
            }
        }
        BARG();

        // ---- finalize (intra-group): 4 threads per site ----
        {
            const int srow = mw * 32 + (wtid >> 2);   // global tile row
            const int q    = wtid & 3;
            float p = pps[q * 128 + srow];            // one nw partial per quad lane
            float ar = 0.0f;
            if (add_ar) {
                #pragma unroll
                for (int jj = 0; jj < 8; jj++) {
                    int j = q * 8 + jj;               // bf16 pair index 0..31
                    uint32_t o = xsw(srow, j * 4);
                    __nv_bfloat162 h = *(__nv_bfloat162*)(smp + XHI_OFF + o);
                    __nv_bfloat162 l = *(__nv_bfloat162*)(smp + XLO_OFF + o);
                    float x0 = __bfloat162float(h.x) + __bfloat162float(l.x);
                    float x1 = __bfloat162float(h.y) + __bfloat162float(l.y);
                    ar = fmaf(x0, ags[2 * j], fmaf(x1, ags[2 * j + 1], ar));
                }
            }
            p  += __shfl_xor_sync(0xffffffffu, p, 1);
            p  += __shfl_xor_sync(0xffffffffu, p, 2);
            ar += __shfl_xor_sync(0xffffffffu, ar, 1);
            ar += __shfl_xor_sync(0xffffffffu, ar, 2);
            if (q == 0)
                outp[base + srow] = ftanh(p + b3v) * max_os + ar;
        }
        BARG();   // X rows reusable by next tile's staging
    }
}

// ---------------------------------------------------------------------------
__global__ void stencil_kernel(const float* __restrict__ xnn,
                               const float* __restrict__ sigma_l,
                               float* __restrict__ outp)
{
    int i = blockIdx.x * blockDim.x + threadIdx.x;
    if (i >= NSITE) return;
    int b = i & 15;
    int z = (i >> 4) & 31;
    int y = (i >> 9) & 31;
    int x = (i >> 14) & 31;
    int xm = (x + 31) & 31, xp = (x + 1) & 31;
    int ym = (y + 31) & 31, yp = (y + 1) & 31;
    int zm = (z + 31) & 31, zp = (z + 1) & 31;

    #define SIDX(X, Y, Z, B) ((((((X) << 5) + (Y)) << 5) + (Z)) * 16 + (B))
    float s = xnn[SIDX(xm, y, zm, b)] + xnn[SIDX(xm, y, zp, b)]
            + xnn[SIDX(xp, y, zm, b)] + xnn[SIDX(xp, y, zp, b)]
            + xnn[SIDX(x, ym, zm, b)] + xnn[SIDX(x, ym, zp, b)]
            + xnn[SIDX(x, yp, zm, b)] + xnn[SIDX(x, yp, zp, b)];
    #undef SIDX

    outp[i] = outp[i] + s * 0.125f;
    outp[NSITE + i] = expf(sigma_l[0]);
}

// ---------------------------------------------------------------------------
extern "C" void kernel_launch(void* const* d_in, const int* in_sizes, int n_in,
                              void* d_out, int out_size)
{
    const float* x_in    = (const float*)d_in[0];
    const float* weight  = (const float*)d_in[1];
    const float* ag      = (const float*)d_in[2];
    const float* W1      = (const float*)d_in[3];
    const float* b1      = (const float*)d_in[4];
    const float* W2      = (const float*)d_in[5];
    const float* b2      = (const float*)d_in[6];
    const float* W3      = (const float*)d_in[7];
    const float* b3      = (const float*)d_in[8];
    const float* W1n     = (const float*)d_in[9];
    const float* b1n     = (const float*)d_in[10];
    const float* W2n     = (const float*)d_in[11];
    const float* b2n     = (const float*)d_in[12];
    const float* W3n     = (const float*)d_in[13];
    const float* b3n     = (const float*)d_in[14];
    const float* max_osl = (const float*)d_in[15];
    const float* sigmal  = (const float*)d_in[16];
    float* out = (float*)d_out;

    cudaFuncSetAttribute(mlp_tc_kernel,
                         cudaFuncAttributeMaxDynamicSharedMemorySize, SMEM_BYTES);

    float* xnn;
    cudaGetSymbolAddress((void**)&xnn, g_xnn);

    mlp_tc_kernel<<<GRID, NTHR, SMEM_BYTES>>>(x_in, weight, W1, b1, W2, b2, W3, b3,
                                              ag, max_osl, out, 1);
    mlp_tc_kernel<<<GRID, NTHR, SMEM_BYTES>>>(x_in, weight, W1n, b1n, W2n, b2n, W3n, b3n,
                                              ag, max_osl, xnn, 0);
    stencil_kernel<<<(NSITE + 255) / 256, 256>>>(xnn, sigmal, out);
}

// round 7
// speedup vs baseline: 5.3412x; 1.4068x over previous
#include <cuda_runtime.h>
#include <cuda_fp16.h>
#include <math.h>
#include <stdint.h>

#define NSITE  524288          // 32*32*32*16
#define TILE   128
#define NTILES 4096
#define GRID   148
#define NTHR   512

// ---- dynamic smem layout (bytes) ----
#define XH_OFF     0           // [128 sites x 64 fp16] 128B rows, swizzled
#define W1H_OFF    16384       // [128 n x 64 k fp16]
#define W1L_OFF    32768
#define W2H_OFF    49152       // [128 n x 128 k fp16] blocked atoms
#define W2L_OFF    81920
#define HH_OFF     114688      // [128 sites x 128 mid fp16] blocked atoms
#define B1S_OFF    147456
#define B2S_OFF    147968
#define W3S_OFF    148480
#define AGS_OFF    148992      // 64 f32
#define PPS_OFF    149248      // 4*128 f32
#define ARP_OFF    151296      // 128 f32 (fp32 AR term per site)
#define SMEM_BYTES 151808

// swizzle: XOR bits[4:6] with bits[7:9] (conflict-free ldmatrix on 128B rows)
__device__ __forceinline__ uint32_t swz(uint32_t o) { return o ^ ((o >> 3) & 0x70); }
// 128B-row tiles (X, W1): row 0..127, colb = byte within row (0..127)
__device__ __forceinline__ uint32_t xsw(int row, int colb) {
    return swz((uint32_t)(row * 128 + colb));
}
// 256B-row tiles (H, W2) in blocked atoms: atom = (row/8) + (colb/128)*16
__device__ __forceinline__ uint32_t hsw(int row, int colb) {
    uint32_t o = (uint32_t)((((row >> 3) + (colb >> 7) * 16) << 10)
                            + ((row & 7) << 7) + (colb & 127));
    return swz(o);
}

// fp16 split: a,b -> hi pair + residual pair
__device__ __forceinline__ void split2h(float a, float b, uint32_t& hi, uint32_t& lo) {
    __half2 h = __floats2half2_rn(a, b);
    float ra = a - __half2float(__low2half(h));
    float rb = b - __half2float(__high2half(h));
    __half2 l = __floats2half2_rn(ra, rb);
    hi = reinterpret_cast<uint32_t&>(h);
    lo = reinterpret_cast<uint32_t&>(l);
}
__device__ __forceinline__ uint32_t pack2h(float a, float b) {
    __half2 h = __floats2half2_rn(a, b);
    return reinterpret_cast<uint32_t&>(h);
}

// tanh via 2 MUFU (ex2 + rcp), abs err ~2e-7
__device__ __forceinline__ float ftanh(float x) {
    float t = __expf(2.0f * x);
    return 1.0f - __fdividef(2.0f, 1.0f + t);
}

#define LDSM4(r, a) \
    asm volatile("ldmatrix.sync.aligned.m8n8.x4.shared.b16 {%0,%1,%2,%3}, [%4];" \
                 : "=r"((r)[0]), "=r"((r)[1]), "=r"((r)[2]), "=r"((r)[3]) : "r"(a))

__device__ __forceinline__ void mma_f16(float* d, const uint32_t* a, const uint32_t* b) {
    asm volatile(
        "mma.sync.aligned.m16n8k16.row.col.f32.f16.f16.f32 "
        "{%0,%1,%2,%3},{%4,%5,%6,%7},{%8,%9},{%0,%1,%2,%3};"
        : "+f"(d[0]), "+f"(d[1]), "+f"(d[2]), "+f"(d[3])
        : "r"(a[0]), "r"(a[1]), "r"(a[2]), "r"(a[3]), "r"(b[0]), "r"(b[1]));
}

// per-group barrier: 4 warps (one per SMSP), IDs 1..4
#define BARG() asm volatile("bar.sync %0, 128;" :: "r"(1 + mw) : "memory")

__device__ float g_xnn[NSITE];

// ---------------------------------------------------------------------------
__global__ __launch_bounds__(NTHR, 1)
void mlp_tc_kernel(const float* __restrict__ xg,
                   const float* __restrict__ weight,
                   const float* __restrict__ W1, const float* __restrict__ b1,
                   const float* __restrict__ W2, const float* __restrict__ b2,
                   const float* __restrict__ W3, const float* __restrict__ b3,
                   const float* __restrict__ ag,
                   const float* __restrict__ max_os_l,
                   float* __restrict__ outp,
                   int add_ar)
{
    extern __shared__ char smp[];
    uint32_t su;
    asm("{ .reg .u64 t; cvta.to.shared.u64 t, %1; cvt.u32.u64 %0, t; }"
        : "=r"(su) : "l"(smp));

    const int tid  = threadIdx.x;
    const int wid  = tid >> 5;
    const int lane = tid & 31;
    const int mw   = wid >> 2;        // group / M block of 32 sites
    const int nw   = wid & 3;         // N block of 32 outputs within group
    const int wtid = nw * 32 + lane;  // 0..127 within group

    // ldmatrix lane geometry
    const int lm = lane >> 3;
    const int lr = lane & 7;
    const int a_row = ((lm & 1) << 3) + lr;
    const int a_kb  = (lm >> 1) << 4;
    const int b_row = ((lm >> 1) << 3) + lr;
    const int b_kb  = (lm & 1) << 4;
    // epilogue geometry
    const int eg = lane >> 2;
    const int ec = (lane & 3) << 1;

    float* b1s  = (float*)(smp + B1S_OFF);
    float* b2s  = (float*)(smp + B2S_OFF);
    float* W3s  = (float*)(smp + W3S_OFF);
    float* ags  = (float*)(smp + AGS_OFF);
    float* pps  = (float*)(smp + PPS_OFF);
    float* arps = (float*)(smp + ARP_OFF);

    // ---- one-time weight prep (fp16 split) ----
    for (int idx = tid; idx < 128 * 32; idx += NTHR) {     // W1 (weight folded in)
        int n = idx >> 5, j = idx & 31;
        float w0 = W1[n * 64 + 2 * j]     * weight[2 * j];
        float w1 = W1[n * 64 + 2 * j + 1] * weight[2 * j + 1];
        uint32_t hi, lo; split2h(w0, w1, hi, lo);
        uint32_t o = xsw(n, j * 4);
        *(uint32_t*)(smp + W1H_OFF + o) = hi;
        *(uint32_t*)(smp + W1L_OFF + o) = lo;
    }
    for (int idx = tid; idx < 128 * 64; idx += NTHR) {     // W2
        int n = idx >> 6, j = idx & 63;
        float w0 = W2[n * 128 + 2 * j];
        float w1 = W2[n * 128 + 2 * j + 1];
        uint32_t hi, lo; split2h(w0, w1, hi, lo);
        uint32_t o = hsw(n, j * 4);
        *(uint32_t*)(smp + W2H_OFF + o) = hi;
        *(uint32_t*)(smp + W2L_OFF + o) = lo;
    }
    if (tid < 128) { b1s[tid] = b1[tid]; b2s[tid] = b2[tid]; W3s[tid] = W3[tid]; }
    if (tid < 64)  ags[tid] = add_ar ? ag[tid] : 0.0f;

    const float max_os = expf(max_os_l[0]);
    const float b3v    = b3[0];
    __syncthreads();

    // intra-group staging coordinates: 4 float4 per thread per tile
    const int s_row = mw * 32 + (wtid >> 2);  // tile row this thread stages
    const int s_f4  = wtid & 3;               // float4 column base
    const int q4    = wtid & 3;

    // ---- prefetch first tile into registers ----
    float4 v[4];
    {
        int t0 = blockIdx.x;
        if (t0 < NTILES) {
            const float4* xg4 = (const float4*)(xg + (size_t)t0 * TILE * 64);
            #pragma unroll
            for (int it = 0; it < 4; it++)
                v[it] = xg4[s_row * 16 + s_f4 + it * 4];
        }
    }

    for (int tile = blockIdx.x; tile < NTILES; tile += gridDim.x) {
        const int base = tile * TILE;

        // ---- stage group's X rows: fp32 -> fp16 (single), AR in fp32 ----
        float arp = 0.0f;
        #pragma unroll
        for (int it = 0; it < 4; it++) {
            int f4 = s_f4 + it * 4;
            *(uint32_t*)(smp + XH_OFF + xsw(s_row, f4 * 8))     = pack2h(v[it].x, v[it].y);
            *(uint32_t*)(smp + XH_OFF + xsw(s_row, f4 * 8 + 4)) = pack2h(v[it].z, v[it].w);
            if (add_ar) {
                const float* agp = ags + f4 * 4;
                arp = fmaf(v[it].x, agp[0], arp);
                arp = fmaf(v[it].y, agp[1], arp);
                arp = fmaf(v[it].z, agp[2], arp);
                arp = fmaf(v[it].w, agp[3], arp);
            }
        }
        if (add_ar) {
            arp += __shfl_xor_sync(0xffffffffu, arp, 1);
            arp += __shfl_xor_sync(0xffffffffu, arp, 2);
            if (q4 == 0) arps[s_row] = arp;
        }
        BARG();

        // ---- prefetch next tile (drains behind the two GEMMs) ----
        {
            int nt = tile + gridDim.x;
            if (nt < NTILES) {
                const float4* xg4 = (const float4*)(xg + (size_t)nt * TILE * 64);
                #pragma unroll
                for (int it = 0; it < 4; it++)
                    v[it] = xg4[s_row * 16 + s_f4 + it * 4];
            }
        }

        // ---- layer 1 GEMM: X(fp16) x (W1h + W1l), K=64 ----
        float d1[2][4][4];
        #pragma unroll
        for (int a = 0; a < 2; a++)
            #pragma unroll
            for (int b = 0; b < 4; b++)
                #pragma unroll
                for (int c = 0; c < 4; c++) d1[a][b][c] = 0.0f;

        #pragma unroll
        for (int kk = 0; kk < 4; kk++) {
            uint32_t Ah[2][4], Bh[2][4], Bl[2][4];
            LDSM4(Ah[0], su + XH_OFF  + xsw(mw * 32 + a_row,      kk * 32 + a_kb));
            LDSM4(Ah[1], su + XH_OFF  + xsw(mw * 32 + 16 + a_row, kk * 32 + a_kb));
            LDSM4(Bh[0], su + W1H_OFF + xsw(nw * 32 + b_row,      kk * 32 + b_kb));
            LDSM4(Bh[1], su + W1H_OFF + xsw(nw * 32 + 16 + b_row, kk * 32 + b_kb));
            LDSM4(Bl[0], su + W1L_OFF + xsw(nw * 32 + b_row,      kk * 32 + b_kb));
            LDSM4(Bl[1], su + W1L_OFF + xsw(nw * 32 + 16 + b_row, kk * 32 + b_kb));
            #pragma unroll
            for (int mb = 0; mb < 2; mb++)
                #pragma unroll
                for (int pr = 0; pr < 2; pr++) {
                    mma_f16(d1[mb][pr * 2 + 0], Ah[mb], &Bh[pr][0]);
                    mma_f16(d1[mb][pr * 2 + 1], Ah[mb], &Bh[pr][2]);
                    mma_f16(d1[mb][pr * 2 + 0], Ah[mb], &Bl[pr][0]);
                    mma_f16(d1[mb][pr * 2 + 1], Ah[mb], &Bl[pr][2]);
                }
        }

        // ---- epilogue 1: tanh -> fp16 H (single precision store) ----
        #pragma unroll
        for (int mb = 0; mb < 2; mb++)
            #pragma unroll
            for (int nc = 0; nc < 4; nc++) {
                int c  = nw * 32 + nc * 8 + ec;
                int r0 = mw * 32 + mb * 16 + eg;
                float* dd = d1[mb][nc];
                float v0 = ftanh(dd[0] + b1s[c]);
                float v1 = ftanh(dd[1] + b1s[c + 1]);
                *(uint32_t*)(smp + HH_OFF + hsw(r0, c * 2)) = pack2h(v0, v1);
                float v2 = ftanh(dd[2] + b1s[c]);
                float v3 = ftanh(dd[3] + b1s[c + 1]);
                *(uint32_t*)(smp + HH_OFF + hsw(r0 + 8, c * 2)) = pack2h(v2, v3);
            }
        BARG();

        // ---- layer 2 GEMM: H(fp16) x (W2h + W2l), K=128 ----
        float d2[2][4][4];
        #pragma unroll
        for (int a = 0; a < 2; a++)
            #pragma unroll
            for (int b = 0; b < 4; b++)
                #pragma unroll
                for (int c = 0; c < 4; c++) d2[a][b][c] = 0.0f;

        #pragma unroll
        for (int kk = 0; kk < 8; kk++) {
            uint32_t Ah[2][4], Bh[2][4], Bl[2][4];
            LDSM4(Ah[0], su + HH_OFF  + hsw(mw * 32 + a_row,      kk * 32 + a_kb));
            LDSM4(Ah[1], su + HH_OFF  + hsw(mw * 32 + 16 + a_row, kk * 32 + a_kb));
            LDSM4(Bh[0], su + W2H_OFF + hsw(nw * 32 + b_row,      kk * 32 + b_kb));
            LDSM4(Bh[1], su + W2H_OFF + hsw(nw * 32 + 16 + b_row, kk * 32 + b_kb));
            LDSM4(Bl[0], su + W2L_OFF + hsw(nw * 32 + b_row,      kk * 32 + b_kb));
            LDSM4(Bl[1], su + W2L_OFF + hsw(nw * 32 + 16 + b_row, kk * 32 + b_kb));
            #pragma unroll
            for (int mb = 0; mb < 2; mb++)
                #pragma unroll
                for (int pr = 0; pr < 2; pr++) {
                    mma_f16(d2[mb][pr * 2 + 0], Ah[mb], &Bh[pr][0]);
                    mma_f16(d2[mb][pr * 2 + 1], Ah[mb], &Bh[pr][2]);
                    mma_f16(d2[mb][pr * 2 + 0], Ah[mb], &Bl[pr][0]);
                    mma_f16(d2[mb][pr * 2 + 1], Ah[mb], &Bl[pr][2]);
                }
        }

        // ---- epilogue 2: tanh, dot with W3, reduce -> pps ----
        {
            float pr[2][2];
            pr[0][0] = pr[0][1] = pr[1][0] = pr[1][1] = 0.0f;
            #pragma unroll
            for (int mb = 0; mb < 2; mb++)
                #pragma unroll
                for (int nc = 0; nc < 4; nc++) {
                    int c = nw * 32 + nc * 8 + ec;
                    float* dd = d2[mb][nc];
                    float w0 = W3s[c], w1 = W3s[c + 1];
                    float bb0 = b2s[c], bb1 = b2s[c + 1];
                    pr[mb][0] += ftanh(dd[0] + bb0) * w0 + ftanh(dd[1] + bb1) * w1;
                    pr[mb][1] += ftanh(dd[2] + bb0) * w0 + ftanh(dd[3] + bb1) * w1;
                }
            #pragma unroll
            for (int mb = 0; mb < 2; mb++)
                #pragma unroll
                for (int h = 0; h < 2; h++) {
                    pr[mb][h] += __shfl_xor_sync(0xffffffffu, pr[mb][h], 1);
                    pr[mb][h] += __shfl_xor_sync(0xffffffffu, pr[mb][h], 2);
                }
            if ((lane & 3) == 0) {
                #pragma unroll
                for (int mb = 0; mb < 2; mb++) {
                    int r0 = mw * 32 + mb * 16 + eg;
                    pps[nw * 128 + r0]     = pr[mb][0];
                    pps[nw * 128 + r0 + 8] = pr[mb][1];
                }
            }
        }
        BARG();

        // ---- finalize (intra-group): 4 threads per site ----
        {
            const int srow = mw * 32 + (wtid >> 2);
            const int q    = wtid & 3;
            float p = pps[q * 128 + srow];
            p += __shfl_xor_sync(0xffffffffu, p, 1);
            p += __shfl_xor_sync(0xffffffffu, p, 2);
            if (q == 0) {
                float ar = add_ar ? arps[srow] : 0.0f;
                outp[base + srow] = ftanh(p + b3v) * max_os + ar;
            }
        }
        BARG();   // X/arps reusable by next tile's staging
    }
}

// ---------------------------------------------------------------------------
__global__ void stencil_kernel(const float* __restrict__ xnn,
                               const float* __restrict__ sigma_l,
                               float* __restrict__ outp)
{
    int i = blockIdx.x * blockDim.x + threadIdx.x;
    if (i >= NSITE) return;
    int b = i & 15;
    int z = (i >> 4) & 31;
    int y = (i >> 9) & 31;
    int x = (i >> 14) & 31;
    int xm = (x + 31) & 31, xp = (x + 1) & 31;
    int ym = (y + 31) & 31, yp = (y + 1) & 31;
    int zm = (z + 31) & 31, zp = (z + 1) & 31;

    #define SIDX(X, Y, Z, B) ((((((X) << 5) + (Y)) << 5) + (Z)) * 16 + (B))
    float s = xnn[SIDX(xm, y, zm, b)] + xnn[SIDX(xm, y, zp, b)]
            + xnn[SIDX(xp, y, zm, b)] + xnn[SIDX(xp, y, zp, b)]
            + xnn[SIDX(x, ym, zm, b)] + xnn[SIDX(x, ym, zp, b)]
            + xnn[SIDX(x, yp, zm, b)] + xnn[SIDX(x, yp, zp, b)];
    #undef SIDX

    outp[i] = outp[i] + s * 0.125f;
    outp[NSITE + i] = expf(sigma_l[0]);
}

// ---------------------------------------------------------------------------
extern "C" void kernel_launch(void* const* d_in, const int* in_sizes, int n_in,
                              void* d_out, int out_size)
{
    const float* x_in    = (const float*)d_in[0];
    const float* weight  = (const float*)d_in[1];
    const float* ag      = (const float*)d_in[2];
    const float* W1      = (const float*)d_in[3];
    const float* b1      = (const float*)d_in[4];
    const float* W2      = (const float*)d_in[5];
    const float* b2      = (const float*)d_in[6];
    const float* W3      = (const float*)d_in[7];
    const float* b3      = (const float*)d_in[8];
    const float* W1n     = (const float*)d_in[9];
    const float* b1n     = (const float*)d_in[10];
    const float* W2n     = (const float*)d_in[11];
    const float* b2n     = (const float*)d_in[12];
    const float* W3n     = (const float*)d_in[13];
    const float* b3n     = (const float*)d_in[14];
    const float* max_osl = (const float*)d_in[15];
    const float* sigmal  = (const float*)d_in[16];
    float* out = (float*)d_out;

    cudaFuncSetAttribute(mlp_tc_kernel,
                         cudaFuncAttributeMaxDynamicSharedMemorySize, SMEM_BYTES);

    float* xnn;
    cudaGetSymbolAddress((void**)&xnn, g_xnn);

    mlp_tc_kernel<<<GRID, NTHR, SMEM_BYTES>>>(x_in, weight, W1, b1, W2, b2, W3, b3,
                                              ag, max_osl, out, 1);
    mlp_tc_kernel<<<GRID, NTHR, SMEM_BYTES>>>(x_in, weight, W1n, b1n, W2n, b2n, W3n, b3n,
                                              ag, max_osl, xnn, 0);
    stencil_kernel<<<(NSITE + 255) / 256, 256>>>(xnn, sigmal, out);
}

// round 8
// speedup vs baseline: 7.1579x; 1.3401x over previous
#include <cuda_runtime.h>
#include <cuda_fp16.h>
#include <math.h>
#include <stdint.h>

#define NSITE  524288          // 32*32*32*16
#define TILE   128
#define NTILES 4096
#define GRID   148
#define NTHR   512

// ---- dynamic smem layout (bytes) ----
#define XH_OFF     0           // [128 sites x 64 fp16] 128B rows, swizzled
#define W1H_OFF    16384       // [128 n x 64 k fp16]
#define W2H_OFF    32768       // [128 n x 128 k fp16] blocked atoms
#define W2L_OFF    65536
#define HH_OFF     98304       // [128 sites x 128 mid fp16] blocked atoms
#define B1S_OFF    131072
#define B2S_OFF    131584
#define W3S_OFF    132096
#define AGS_OFF    132608      // 64 f32
#define PPS_OFF    132864      // 4*128 f32
#define ARP_OFF    134912      // 128 f32 (fp32 AR term per site)
#define SMEM_BYTES 135424

// swizzle: XOR bits[4:6] with bits[7:9] (conflict-free ldmatrix on 128B rows)
__device__ __forceinline__ uint32_t swz(uint32_t o) { return o ^ ((o >> 3) & 0x70); }
// 128B-row tiles (X, W1): row 0..127, colb = byte within row (0..127)
__device__ __forceinline__ uint32_t xsw(int row, int colb) {
    return swz((uint32_t)(row * 128 + colb));
}
// 256B-row tiles (H, W2) in blocked atoms: atom = (row/8) + (colb/128)*16
__device__ __forceinline__ uint32_t hsw(int row, int colb) {
    uint32_t o = (uint32_t)((((row >> 3) + (colb >> 7) * 16) << 10)
                            + ((row & 7) << 7) + (colb & 127));
    return swz(o);
}

// fp16 split: a,b -> hi pair + residual pair
__device__ __forceinline__ void split2h(float a, float b, uint32_t& hi, uint32_t& lo) {
    __half2 h = __floats2half2_rn(a, b);
    float ra = a - __half2float(__low2half(h));
    float rb = b - __half2float(__high2half(h));
    __half2 l = __floats2half2_rn(ra, rb);
    hi = reinterpret_cast<uint32_t&>(h);
    lo = reinterpret_cast<uint32_t&>(l);
}
__device__ __forceinline__ uint32_t pack2h(float a, float b) {
    __half2 h = __floats2half2_rn(a, b);
    return reinterpret_cast<uint32_t&>(h);
}

// accurate tanh via 2 MUFU (ex2 + rcp) — used only for the final output
__device__ __forceinline__ float ftanh(float x) {
    float t = __expf(2.0f * x);
    return 1.0f - __fdividef(2.0f, 1.0f + t);
}
// fast tanh: single MUFU, max abs err ~5e-4 — hidden activations only
__device__ __forceinline__ float ftanha(float x) {
    float y;
    asm("tanh.approx.f32 %0, %1;" : "=f"(y) : "f"(x));
    return y;
}

#define LDSM4(r, a) \
    asm volatile("ldmatrix.sync.aligned.m8n8.x4.shared.b16 {%0,%1,%2,%3}, [%4];" \
                 : "=r"((r)[0]), "=r"((r)[1]), "=r"((r)[2]), "=r"((r)[3]) : "r"(a))

__device__ __forceinline__ void mma_f16(float* d, const uint32_t* a, const uint32_t* b) {
    asm volatile(
        "mma.sync.aligned.m16n8k16.row.col.f32.f16.f16.f32 "
        "{%0,%1,%2,%3},{%4,%5,%6,%7},{%8,%9},{%0,%1,%2,%3};"
        : "+f"(d[0]), "+f"(d[1]), "+f"(d[2]), "+f"(d[3])
        : "r"(a[0]), "r"(a[1]), "r"(a[2]), "r"(a[3]), "r"(b[0]), "r"(b[1]));
}

// per-group barrier: 4 warps (one per SMSP), IDs 1..4
#define BARG() asm volatile("bar.sync %0, 128;" :: "r"(1 + mw) : "memory")

__device__ float g_xnn[NSITE];

// ---------------------------------------------------------------------------
__global__ __launch_bounds__(NTHR, 1)
void mlp_tc_kernel(const float* __restrict__ xg,
                   const float* __restrict__ weight,
                   const float* __restrict__ W1, const float* __restrict__ b1,
                   const float* __restrict__ W2, const float* __restrict__ b2,
                   const float* __restrict__ W3, const float* __restrict__ b3,
                   const float* __restrict__ ag,
                   const float* __restrict__ max_os_l,
                   float* __restrict__ outp,
                   int add_ar)
{
    extern __shared__ char smp[];
    uint32_t su;
    asm("{ .reg .u64 t; cvta.to.shared.u64 t, %1; cvt.u32.u64 %0, t; }"
        : "=r"(su) : "l"(smp));

    const int tid  = threadIdx.x;
    const int wid  = tid >> 5;
    const int lane = tid & 31;
    const int mw   = wid >> 2;        // group / M block of 32 sites
    const int nw   = wid & 3;         // N block of 32 outputs within group
    const int wtid = nw * 32 + lane;  // 0..127 within group

    // ldmatrix lane geometry
    const int lm = lane >> 3;
    const int lr = lane & 7;
    const int a_row = ((lm & 1) << 3) + lr;
    const int a_kb  = (lm >> 1) << 4;
    const int b_row = ((lm >> 1) << 3) + lr;
    const int b_kb  = (lm & 1) << 4;
    // epilogue geometry
    const int eg = lane >> 2;
    const int ec = (lane & 3) << 1;

    float* b1s  = (float*)(smp + B1S_OFF);
    float* b2s  = (float*)(smp + B2S_OFF);
    float* W3s  = (float*)(smp + W3S_OFF);
    float* ags  = (float*)(smp + AGS_OFF);
    float* pps  = (float*)(smp + PPS_OFF);
    float* arps = (float*)(smp + ARP_OFF);

    // ---- one-time weight prep ----
    for (int idx = tid; idx < 128 * 32; idx += NTHR) {     // W1 single fp16, weight folded
        int n = idx >> 5, j = idx & 31;
        float w0 = W1[n * 64 + 2 * j]     * weight[2 * j];
        float w1 = W1[n * 64 + 2 * j + 1] * weight[2 * j + 1];
        *(uint32_t*)(smp + W1H_OFF + xsw(n, j * 4)) = pack2h(w0, w1);
    }
    for (int idx = tid; idx < 128 * 64; idx += NTHR) {     // W2 split fp16
        int n = idx >> 6, j = idx & 63;
        float w0 = W2[n * 128 + 2 * j];
        float w1 = W2[n * 128 + 2 * j + 1];
        uint32_t hi, lo; split2h(w0, w1, hi, lo);
        uint32_t o = hsw(n, j * 4);
        *(uint32_t*)(smp + W2H_OFF + o) = hi;
        *(uint32_t*)(smp + W2L_OFF + o) = lo;
    }
    if (tid < 128) { b1s[tid] = b1[tid]; b2s[tid] = b2[tid]; W3s[tid] = W3[tid]; }
    if (tid < 64)  ags[tid] = add_ar ? ag[tid] : 0.0f;

    const float max_os = expf(max_os_l[0]);
    const float b3v    = b3[0];
    __syncthreads();

    // intra-group staging coordinates: 4 float4 per thread per tile
    const int s_row = mw * 32 + (wtid >> 2);  // tile row this thread stages
    const int s_f4  = wtid & 3;               // float4 column base
    const int q4    = wtid & 3;

    // ---- prefetch first tile into registers ----
    float4 v[4];
    {
        int t0 = blockIdx.x;
        if (t0 < NTILES) {
            const float4* xg4 = (const float4*)(xg + (size_t)t0 * TILE * 64);
            #pragma unroll
            for (int it = 0; it < 4; it++)
                v[it] = xg4[s_row * 16 + s_f4 + it * 4];
        }
    }

    for (int tile = blockIdx.x; tile < NTILES; tile += gridDim.x) {
        const int base = tile * TILE;

        // ---- stage group's X rows: fp32 -> fp16 (single), AR in fp32 ----
        float arp = 0.0f;
        #pragma unroll
        for (int it = 0; it < 4; it++) {
            int f4 = s_f4 + it * 4;
            *(uint32_t*)(smp + XH_OFF + xsw(s_row, f4 * 8))     = pack2h(v[it].x, v[it].y);
            *(uint32_t*)(smp + XH_OFF + xsw(s_row, f4 * 8 + 4)) = pack2h(v[it].z, v[it].w);
            if (add_ar) {
                const float* agp = ags + f4 * 4;
                arp = fmaf(v[it].x, agp[0], arp);
                arp = fmaf(v[it].y, agp[1], arp);
                arp = fmaf(v[it].z, agp[2], arp);
                arp = fmaf(v[it].w, agp[3], arp);
            }
        }
        if (add_ar) {
            arp += __shfl_xor_sync(0xffffffffu, arp, 1);
            arp += __shfl_xor_sync(0xffffffffu, arp, 2);
            if (q4 == 0) arps[s_row] = arp;
        }
        BARG();

        // ---- prefetch next tile (drains behind the two GEMMs) ----
        {
            int nt = tile + gridDim.x;
            if (nt < NTILES) {
                const float4* xg4 = (const float4*)(xg + (size_t)nt * TILE * 64);
                #pragma unroll
                for (int it = 0; it < 4; it++)
                    v[it] = xg4[s_row * 16 + s_f4 + it * 4];
            }
        }

        // ---- layer 1 GEMM: X(fp16) x W1(fp16), K=64 ----
        float d1[2][4][4];
        #pragma unroll
        for (int a = 0; a < 2; a++)
            #pragma unroll
            for (int b = 0; b < 4; b++)
                #pragma unroll
                for (int c = 0; c < 4; c++) d1[a][b][c] = 0.0f;

        #pragma unroll
        for (int kk = 0; kk < 4; kk++) {
            uint32_t Ah[2][4], Bh[2][4];
            LDSM4(Ah[0], su + XH_OFF  + xsw(mw * 32 + a_row,      kk * 32 + a_kb));
            LDSM4(Ah[1], su + XH_OFF  + xsw(mw * 32 + 16 + a_row, kk * 32 + a_kb));
            LDSM4(Bh[0], su + W1H_OFF + xsw(nw * 32 + b_row,      kk * 32 + b_kb));
            LDSM4(Bh[1], su + W1H_OFF + xsw(nw * 32 + 16 + b_row, kk * 32 + b_kb));
            #pragma unroll
            for (int mb = 0; mb < 2; mb++)
                #pragma unroll
                for (int pr = 0; pr < 2; pr++) {
                    mma_f16(d1[mb][pr * 2 + 0], Ah[mb], &Bh[pr][0]);
                    mma_f16(d1[mb][pr * 2 + 1], Ah[mb], &Bh[pr][2]);
                }
        }

        // ---- epilogue 1: fast tanh -> fp16 H ----
        #pragma unroll
        for (int mb = 0; mb < 2; mb++)
            #pragma unroll
            for (int nc = 0; nc < 4; nc++) {
                int c  = nw * 32 + nc * 8 + ec;
                int r0 = mw * 32 + mb * 16 + eg;
                float* dd = d1[mb][nc];
                float v0 = ftanha(dd[0] + b1s[c]);
                float v1 = ftanha(dd[1] + b1s[c + 1]);
                *(uint32_t*)(smp + HH_OFF + hsw(r0, c * 2)) = pack2h(v0, v1);
                float v2 = ftanha(dd[2] + b1s[c]);
                float v3 = ftanha(dd[3] + b1s[c + 1]);
                *(uint32_t*)(smp + HH_OFF + hsw(r0 + 8, c * 2)) = pack2h(v2, v3);
            }
        BARG();

        // ---- layer 2 GEMM: H(fp16) x (W2h + W2l), K=128 ----
        float d2[2][4][4];
        #pragma unroll
        for (int a = 0; a < 2; a++)
            #pragma unroll
            for (int b = 0; b < 4; b++)
                #pragma unroll
                for (int c = 0; c < 4; c++) d2[a][b][c] = 0.0f;

        #pragma unroll
        for (int kk = 0; kk < 8; kk++) {
            uint32_t Ah[2][4], Bh[2][4], Bl[2][4];
            LDSM4(Ah[0], su + HH_OFF  + hsw(mw * 32 + a_row,      kk * 32 + a_kb));
            LDSM4(Ah[1], su + HH_OFF  + hsw(mw * 32 + 16 + a_row, kk * 32 + a_kb));
            LDSM4(Bh[0], su + W2H_OFF + hsw(nw * 32 + b_row,      kk * 32 + b_kb));
            LDSM4(Bh[1], su + W2H_OFF + hsw(nw * 32 + 16 + b_row, kk * 32 + b_kb));
            LDSM4(Bl[0], su + W2L_OFF + hsw(nw * 32 + b_row,      kk * 32 + b_kb));
            LDSM4(Bl[1], su + W2L_OFF + hsw(nw * 32 + 16 + b_row, kk * 32 + b_kb));
            #pragma unroll
            for (int mb = 0; mb < 2; mb++)
                #pragma unroll
                for (int pr = 0; pr < 2; pr++) {
                    mma_f16(d2[mb][pr * 2 + 0], Ah[mb], &Bh[pr][0]);
                    mma_f16(d2[mb][pr * 2 + 1], Ah[mb], &Bh[pr][2]);
                    mma_f16(d2[mb][pr * 2 + 0], Ah[mb], &Bl[pr][0]);
                    mma_f16(d2[mb][pr * 2 + 1], Ah[mb], &Bl[pr][2]);
                }
        }

        // ---- epilogue 2: fast tanh, dot with W3, reduce -> pps ----
        {
            float pr[2][2];
            pr[0][0] = pr[0][1] = pr[1][0] = pr[1][1] = 0.0f;
            #pragma unroll
            for (int mb = 0; mb < 2; mb++)
                #pragma unroll
                for (int nc = 0; nc < 4; nc++) {
                    int c = nw * 32 + nc * 8 + ec;
                    float* dd = d2[mb][nc];
                    float w0 = W3s[c], w1 = W3s[c + 1];
                    float bb0 = b2s[c], bb1 = b2s[c + 1];
                    pr[mb][0] += ftanha(dd[0] + bb0) * w0 + ftanha(dd[1] + bb1) * w1;
                    pr[mb][1] += ftanha(dd[2] + bb0) * w0 + ftanha(dd[3] + bb1) * w1;
                }
            #pragma unroll
            for (int mb = 0; mb < 2; mb++)
                #pragma unroll
                for (int h = 0; h < 2; h++) {
                    pr[mb][h] += __shfl_xor_sync(0xffffffffu, pr[mb][h], 1);
                    pr[mb][h] += __shfl_xor_sync(0xffffffffu, pr[mb][h], 2);
                }
            if ((lane & 3) == 0) {
                #pragma unroll
                for (int mb = 0; mb < 2; mb++) {
                    int r0 = mw * 32 + mb * 16 + eg;
                    pps[nw * 128 + r0]     = pr[mb][0];
                    pps[nw * 128 + r0 + 8] = pr[mb][1];
                }
            }
        }
        BARG();

        // ---- finalize (intra-group): 4 threads per site, accurate tanh ----
        {
            const int srow = mw * 32 + (wtid >> 2);
            const int q    = wtid & 3;
            float p = pps[q * 128 + srow];
            p += __shfl_xor_sync(0xffffffffu, p, 1);
            p += __shfl_xor_sync(0xffffffffu, p, 2);
            if (q == 0) {
                float ar = add_ar ? arps[srow] : 0.0f;
                outp[base + srow] = ftanh(p + b3v) * max_os + ar;
            }
        }
        BARG();   // X/arps reusable by next tile's staging
    }
}

// ---------------------------------------------------------------------------
__global__ void stencil_kernel(const float* __restrict__ xnn,
                               const float* __restrict__ sigma_l,
                               float* __restrict__ outp)
{
    int i = blockIdx.x * blockDim.x + threadIdx.x;
    if (i >= NSITE) return;
    int b = i & 15;
    int z = (i >> 4) & 31;
    int y = (i >> 9) & 31;
    int x = (i >> 14) & 31;
    int xm = (x + 31) & 31, xp = (x + 1) & 31;
    int ym = (y + 31) & 31, yp = (y + 1) & 31;
    int zm = (z + 31) & 31, zp = (z + 1) & 31;

    #define SIDX(X, Y, Z, B) ((((((X) << 5) + (Y)) << 5) + (Z)) * 16 + (B))
    float s = xnn[SIDX(xm, y, zm, b)] + xnn[SIDX(xm, y, zp, b)]
            + xnn[SIDX(xp, y, zm, b)] + xnn[SIDX(xp, y, zp, b)]
            + xnn[SIDX(x, ym, zm, b)] + xnn[SIDX(x, ym, zp, b)]
            + xnn[SIDX(x, yp, zm, b)] + xnn[SIDX(x, yp, zp, b)];
    #undef SIDX

    outp[i] = outp[i] + s * 0.125f;
    outp[NSITE + i] = expf(sigma_l[0]);
}

// ---------------------------------------------------------------------------
extern "C" void kernel_launch(void* const* d_in, const int* in_sizes, int n_in,
                              void* d_out, int out_size)
{
    const float* x_in    = (const float*)d_in[0];
    const float* weight  = (const float*)d_in[1];
    const float* ag      = (const float*)d_in[2];
    const float* W1      = (const float*)d_in[3];
    const float* b1      = (const float*)d_in[4];
    const float* W2      = (const float*)d_in[5];
    const float* b2      = (const float*)d_in[6];
    const float* W3      = (const float*)d_in[7];
    const float* b3      = (const float*)d_in[8];
    const float* W1n     = (const float*)d_in[9];
    const float* b1n     = (const float*)d_in[10];
    const float* W2n     = (const float*)d_in[11];
    const float* b2n     = (const float*)d_in[12];
    const float* W3n     = (const float*)d_in[13];
    const float* b3n     = (const float*)d_in[14];
    const float* max_osl = (const float*)d_in[15];
    const float* sigmal  = (const float*)d_in[16];
    float* out = (float*)d_out;

    cudaFuncSetAttribute(mlp_tc_kernel,
                         cudaFuncAttributeMaxDynamicSharedMemorySize, SMEM_BYTES);

    float* xnn;
    cudaGetSymbolAddress((void**)&xnn, g_xnn);

    mlp_tc_kernel<<<GRID, NTHR, SMEM_BYTES>>>(x_in, weight, W1, b1, W2, b2, W3, b3,
                                              ag, max_osl, out, 1);
    mlp_tc_kernel<<<GRID, NTHR, SMEM_BYTES>>>(x_in, weight, W1n, b1n, W2n, b2n, W3n, b3n,
                                              ag, max_osl, xnn, 0);
    stencil_kernel<<<(NSITE + 255) / 256, 256>>>(xnn, sigmal, out);
}